// round 4
// baseline (speedup 1.0000x reference)
#include <cuda_runtime.h>
#include <math.h>

#define EPSV  1e-20f
#define L2EPS -66.438561897f
#define Hh 192
#define Ww 192
#define HW (Hh*Ww)

__device__ float g_wcd[1024];     // channel_d [o][i]
__device__ float g_wsd[288];      // spatial_d [i][k]
__device__ float g_wce[1024];     // channel_e [o][i]
__device__ float g_wdir[512];     // [p][i][d]
__device__ float g_wse[1152];     // [i][d][k]
__device__ float g_wprop[128];    // [i][d]
__device__ float g_wpow0[128];    // [i][d]
__device__ float g_wpow1[128];    // [i][d]
__device__ float g_cein [2*32*4*HW];
__device__ float g_ecein[2*32*4*HW];

__device__ __forceinline__ float sp_(float v){ return log1pf(expf(v)); }
__device__ __forceinline__ float sig_(float v){ return 1.f/(1.f+expf(-v)); }
__device__ __forceinline__ float ex2_(float v){
    float r; asm("ex2.approx.f32 %0, %1;" : "=f"(r) : "f"(v)); return r;
}

// ---------------- prep: 5 warps, lane = channel ----------------
__global__ void prep_kernel(const float* __restrict__ Wcd, const float* __restrict__ Wsd,
                            const float* __restrict__ Wce, const float* __restrict__ Wse0,
                            const float* __restrict__ Wse1, const float* __restrict__ Wse3,
                            const float* __restrict__ Wdir, const float* __restrict__ Wpow,
                            const float* __restrict__ Wprop)
{
    int t = threadIdx.x & 31;
    int w = threadIdx.x >> 5;
    if (w == 0) { // channel_d row o=t
        float s=0.f; for(int i=0;i<32;i++) s+=sp_(Wcd[t*32+i]);
        float inv=1.f/s; for(int i=0;i<32;i++) g_wcd[t*32+i]=sp_(Wcd[t*32+i])*inv;
    } else if (w == 1) { // channel_e row o=t
        float s=0.f; for(int i=0;i<32;i++) s+=sp_(Wce[t*32+i]);
        float inv=1.f/s; for(int i=0;i<32;i++) g_wce[t*32+i]=sp_(Wce[t*32+i])*inv;
    } else if (w == 2) { // spatial_d + prop/pow, i=t
        float v[9]; float s=0.f;
        for(int h=0;h<3;h++){
            float a=sp_(Wsd[t*6+h*2+0]), b=sp_(Wsd[t*6+h*2+1]);
            v[h*3+0]=a; v[h*3+1]=b; v[h*3+2]=a;
        }
        for(int k=0;k<9;k++) s+=v[k];
        float inv=1.f/s; for(int k=0;k<9;k++) g_wsd[t*9+k]=v[k]*inv;
        float s0=sig_(Wprop[t*3+0]), s1=sig_(Wprop[t*3+1]), s2=sig_(Wprop[t*3+2]);
        g_wprop[t*4+0]=s1; g_wprop[t*4+1]=s0; g_wprop[t*4+2]=s1; g_wprop[t*4+3]=s2;
        float p0=sp_(Wpow[t*5+0]),p1=sp_(Wpow[t*5+1]),p2=sp_(Wpow[t*5+2]),
              p3=sp_(Wpow[t*5+3]),p4=sp_(Wpow[t*5+4]);
        g_wpow0[t*4+0]=p0; g_wpow0[t*4+1]=p2; g_wpow0[t*4+2]=p1; g_wpow0[t*4+3]=p4;
        g_wpow1[t*4+0]=p1; g_wpow1[t*4+1]=p3; g_wpow1[t*4+2]=p0; g_wpow1[t*4+3]=p4;
    } else if (w == 3) { // dir, i=t
        float d[10]; for(int j=0;j<10;j++) d[j]=sp_(Wdir[t*10+j]);
        float rows[4][4]={{d[0],d[1],d[2],d[3]},{d[4],d[5],d[4],d[6]},
                          {d[2],d[1],d[0],d[3]},{d[7],d[8],d[7],d[9]}};
        for(int p=0;p<4;p++){
            float s=rows[p][0]+rows[p][1]+rows[p][2]+rows[p][3];
            float inv=1.f/s;
            for(int dd=0;dd<4;dd++) g_wdir[(p*32+t)*4+dd]=rows[p][dd]*inv;
        }
    } else if (w == 4) { // spatial_e, i=t
        float se0[9],se1v[9],se3v[9],se2[9];
        for(int k=0;k<9;k++) se0[k]=sp_(Wse0[t*9+k]);
        for(int h=0;h<3;h++){
            float a=sp_(Wse1[t*6+h*2+0]), b=sp_(Wse1[t*6+h*2+1]);
            se1v[h*3+0]=a; se1v[h*3+1]=b; se1v[h*3+2]=a;
            float a3=sp_(Wse3[t*6+h*2+0]), b3=sp_(Wse3[t*6+h*2+1]);
            se3v[h*3+0]=a3; se3v[h*3+1]=b3; se3v[h*3+2]=a3;
            se2[h*3+0]=se0[h*3+2]; se2[h*3+1]=se0[h*3+1]; se2[h*3+2]=se0[h*3+0];
        }
        const float* arr[4]={se0,se1v,se2,se3v};
        for(int dd=0;dd<4;dd++){
            float s=0.f; for(int k=0;k<9;k++) s+=arr[dd][k];
            float inv=1.f/s;
            for(int k=0;k<9;k++) g_wse[(t*4+dd)*9+k]=arr[dd][k]*inv;
        }
    }
}

// ---------------- K1: vectorized, 8 px/thread ----------------
__global__ void __launch_bounds__(256) k1_prepin(const float* __restrict__ x,
                                                 const float* __restrict__ ece,
                                                 const float* __restrict__ ce)
{
    int plane = blockIdx.y;                 // b*32+i, 0..63
    int i = plane & 31;
    int g = blockIdx.x*256 + threadIdx.x;   // 18*256 = 4608
    int y = g/24, xg = (g - y*24)*8;
    const float* dcd = x + (size_t)plane*HW;
    const float* cdp = x + (size_t)(64+plane)*HW;

    // lv/cv windows: cols xg-1 .. xg+8 (idx 0..9), rows y-1..y+1
    float lv[3][10], cv[3][10];
#pragma unroll
    for(int r=0;r<3;r++){
        int yy=y-1+r;
        bool yok=((unsigned)yy<(unsigned)Hh);
        const float* rd0=dcd+yy*Ww;
        const float* rc0=cdp+yy*Ww;
        float rd[16],rc[16];
#pragma unroll
        for(int seg=0;seg<4;seg++){
            int xs=xg-4+seg*4;
            float4 vd=make_float4(0.f,0.f,0.f,0.f), vc=vd;
            if(yok&&(unsigned)xs<(unsigned)Ww){
                vd=*reinterpret_cast<const float4*>(rd0+xs);
                vc=*reinterpret_cast<const float4*>(rc0+xs);
            }
            rd[seg*4]=vd.x; rd[seg*4+1]=vd.y; rd[seg*4+2]=vd.z; rd[seg*4+3]=vd.w;
            rc[seg*4]=vc.x; rc[seg*4+1]=vc.y; rc[seg*4+2]=vc.z; rc[seg*4+3]=vc.w;
        }
#pragma unroll
        for(int idx=0;idx<10;idx++){
            float dc=rd[idx+3], c=rc[idx+3];
            cv[r][idx]=c;
            float l=__log2f(dc)-__log2f(c+EPSV);
            lv[r][idx]=(dc>0.f)? l : -1e30f;
        }
    }
    // dir mapping (output col j -> idx j+1): A/B (row, idx-shift)
    // d0: A=(0,j)   B=(2,j+2);  d1: A=(0,j+1) B=(2,j+1)
    // d2: A=(0,j+2) B=(2,j);    d3: A=(1,j+2) B=(1,j)
    const int Ar[4]={0,0,0,1}, Ac[4]={0,1,2,2};
    const int Br[4]={2,2,2,1}, Bc[4]={2,1,0,0};
    size_t base=(size_t)plane*4*HW + y*Ww + xg;
#pragma unroll
    for(int d=0;d<4;d++){
        float p0=g_wpow0[i*4+d], p1=g_wpow1[i*4+d], wp=g_wprop[i*4+d];
        size_t off=base+(size_t)d*HW;
        float4 cea=*reinterpret_cast<const float4*>(ce+off);
        float4 ceb=*reinterpret_cast<const float4*>(ce+off+4);
        float4 eca=*reinterpret_cast<const float4*>(ece+off);
        float4 ecb=*reinterpret_cast<const float4*>(ece+off+4);
        float cei[8]={cea.x,cea.y,cea.z,cea.w,ceb.x,ceb.y,ceb.z,ceb.w};
        float eci[8]={eca.x,eca.y,eca.z,eca.w,ecb.x,ecb.y,ecb.z,ecb.w};
        float oc[8],oe[8];
#pragma unroll
        for(int j=0;j<8;j++){
            float lA=lv[Ar[d]][j+Ac[d]], lB=lv[Br[d]][j+Bc[d]];
            float la=fminf(fmaxf(lA-fmaxf(lB,L2EPS),L2EPS),0.f);
            float lb=fminf(fmaxf(lB-fmaxf(lA,L2EPS),L2EPS),0.f);
            float en=ex2_(fminf(p0*la,p1*lb));
            float cn=cv[Ar[d]][j+Ac[d]]*cv[Br[d]][j+Bc[d]];
            oc[j]=cei[j]*wp+cn*(1.f-wp);
            oe[j]=eci[j]*wp+en*cn*(1.f-wp);
        }
        *reinterpret_cast<float4*>(g_cein+off)   =make_float4(oc[0],oc[1],oc[2],oc[3]);
        *reinterpret_cast<float4*>(g_cein+off+4) =make_float4(oc[4],oc[5],oc[6],oc[7]);
        *reinterpret_cast<float4*>(g_ecein+off)  =make_float4(oe[0],oe[1],oe[2],oe[3]);
        *reinterpret_cast<float4*>(g_ecein+off+4)=make_float4(oe[4],oe[5],oe[6],oe[7]);
    }
}

// ---------------- K23 fused: conv_e (both tensors) + e + d-conv + mixes ----------------
// dynamic smem carve:
//   sh4  : 2112 float4 (33792 B)   phase A->B staging [pix][i] over p
//   shce : 2048 float4 (32768 B)   ce_out stash [(p*2+h)*256 + tid]
//   shw  : 4000 float  (16000 B)   wse(1152) wdir(512) wceT(1024) wcdT(1024) wsd(288)
#define K23_SMEM (33792+32768+16000)

__global__ void __launch_bounds__(256) k23_fused(const float* __restrict__ x,
                                                 float* __restrict__ dout)
{
    extern __shared__ char dsm[];
    float4* sh4 =(float4*)dsm;
    float4* shce=(float4*)(dsm+33792);
    float*  shw =(float*)(dsm+33792+32768);
    float* sh_wse =shw;
    float* sh_wdir=shw+1152;
    float* sh_wceT=shw+1664;
    float* sh_wcdT=shw+2688;
    float* sh_wsd =shw+3712;
    int tid=threadIdx.x;
    for(int k=tid;k<1152;k+=256) sh_wse[k]=g_wse[k];
    for(int k=tid;k<512;k+=256)  sh_wdir[k]=g_wdir[k];
    for(int k=tid;k<1024;k+=256) sh_wceT[k]=g_wce[(k&31)*32+(k>>5)];
    for(int k=tid;k<1024;k+=256) sh_wcdT[k]=g_wcd[(k&31)*32+(k>>5)];
    for(int k=tid;k<288;k+=256)  sh_wsd[k]=g_wsd[k];
    int t=blockIdx.x;
    int b=t/576; int rem=t-b*576;
    int y0=rem/3; int x0=(rem-y0*3)*64;
    int i=tid>>3, px8=tid&7;
    int xb=x0+px8*8;
    int o=tid&31, pg=tid>>5;
    __syncthreads();

    const size_t ece_off=(size_t)128*HW;
    const size_t ceo_off=(size_t)384*HW;

    float acc_ece[4][8];

    for(int sel=0;sel<2;sel++){
        const float* __restrict__ in = sel ? g_ecein : g_cein;
        float tacc[4][8];
#pragma unroll
        for(int p=0;p<4;p++)
#pragma unroll
            for(int j=0;j<8;j++) tacc[p][j]=0.f;
#pragma unroll
        for(int d=0;d<4;d++){
            const float* ch = in + (size_t)((b*32+i)*4+d)*HW;
            const float* w = sh_wse + (i*4+d)*9;
            float s[8];
#pragma unroll
            for(int j=0;j<8;j++) s[j]=0.f;
#pragma unroll
            for(int ry=0;ry<3;ry++){
                int yy=y0+ry-1;
                bool yok=((unsigned)yy<(unsigned)Hh);
                const float* rp=ch+yy*Ww;
                float r[16];
#pragma unroll
                for(int seg=0;seg<4;seg++){
                    int xs=xb-4+seg*4;
                    float4 v=make_float4(0.f,0.f,0.f,0.f);
                    if(yok&&(unsigned)xs<(unsigned)Ww)
                        v=*reinterpret_cast<const float4*>(rp+xs);
                    r[seg*4]=v.x; r[seg*4+1]=v.y; r[seg*4+2]=v.z; r[seg*4+3]=v.w;
                }
                float w0=w[ry*3],w1=w[ry*3+1],w2=w[ry*3+2];
#pragma unroll
                for(int j=0;j<8;j++)
                    s[j]+=w0*r[j+3]+w1*r[j+4]+w2*r[j+5];
            }
#pragma unroll
            for(int p=0;p<4;p++){
                float wd=sh_wdir[(p*32+i)*4+d];
#pragma unroll
                for(int j=0;j<8;j++) tacc[p][j]+=wd*s[j];
            }
        }
#pragma unroll
        for(int j=0;j<8;j++)
            sh4[(px8*8+j)*33+i]=make_float4(tacc[0][j],tacc[1][j],tacc[2][j],tacc[3][j]);
        __syncthreads();

        // channel mix: o = tid&31, broadcast smem reads
        float acc[4][8];
#pragma unroll
        for(int p=0;p<4;p++)
#pragma unroll
            for(int j=0;j<8;j++) acc[p][j]=0.f;
#pragma unroll 4
        for(int ii=0;ii<32;ii++){
            float wv=sh_wceT[ii*32+o];
#pragma unroll
            for(int j=0;j<8;j++){
                float4 tv=sh4[(pg*8+j)*33+ii];
                acc[0][j]+=wv*tv.x; acc[1][j]+=wv*tv.y;
                acc[2][j]+=wv*tv.z; acc[3][j]+=wv*tv.w;
            }
        }
        size_t ooff = sel ? ece_off : ceo_off;
#pragma unroll
        for(int p=0;p<4;p++){
            float* op=dout+ooff+(size_t)((b*32+o)*4+p)*HW+y0*Ww+x0+pg*8;
            *reinterpret_cast<float4*>(op)  =make_float4(acc[p][0],acc[p][1],acc[p][2],acc[p][3]);
            *reinterpret_cast<float4*>(op+4)=make_float4(acc[p][4],acc[p][5],acc[p][6],acc[p][7]);
        }
        if(sel==0){ // stash ce_out in smem (own-thread slots, conflict-free)
#pragma unroll
            for(int p=0;p<4;p++){
                shce[(p*2+0)*256+tid]=make_float4(acc[p][0],acc[p][1],acc[p][2],acc[p][3]);
                shce[(p*2+1)*256+tid]=make_float4(acc[p][4],acc[p][5],acc[p][6],acc[p][7]);
            }
        } else {
#pragma unroll
            for(int p=0;p<4;p++)
#pragma unroll
                for(int j=0;j<8;j++) acc_ece[p][j]=acc[p][j];
        }
        __syncthreads();   // protect sh4 reuse (sel1 phase A / phase C alias)
    }

    // ---- phase C: e = clip(ece_out/ce_out), e9-modulated depthwise of dcd/cd ----
    float e[5][8];
#pragma unroll
    for(int j=0;j<8;j++) e[4][j]=1.f;
#pragma unroll
    for(int p=0;p<4;p++){
#pragma unroll
        for(int h=0;h<2;h++){
            float4 cv4=shce[(p*2+h)*256+tid];
            float cvv[4]={cv4.x,cv4.y,cv4.z,cv4.w};
#pragma unroll
            for(int l=0;l<4;l++){
                int j=h*4+l;
                e[p][j]=fminf(fmaxf(__fdividef(acc_ece[p][j],cvv[l]+EPSV),EPSV),1.f);
            }
        }
    }
    int xc=x0+pg*8;
    const float* dcd=x+(size_t)(b*32+o)*HW;
    const float* cdp=x+(size_t)(64+b*32+o)*HW;
    const float* w=sh_wsd+o*9;
    float md[8],mc[8];
#pragma unroll
    for(int j=0;j<8;j++){ md[j]=0.f; mc[j]=0.f; }
    const int emap[9]={0,1,2,3,4,3,2,1,0};
#pragma unroll
    for(int ry=0;ry<3;ry++){
        int yy=y0+ry-1;
        bool yok=((unsigned)yy<(unsigned)Hh);
        const float* rpd=dcd+yy*Ww;
        const float* rpc=cdp+yy*Ww;
        float rd[16],rc[16];
#pragma unroll
        for(int seg=0;seg<4;seg++){
            int xs=xc-4+seg*4;
            float4 vd=make_float4(0.f,0.f,0.f,0.f), vc=vd;
            if(yok&&(unsigned)xs<(unsigned)Ww){
                vd=*reinterpret_cast<const float4*>(rpd+xs);
                vc=*reinterpret_cast<const float4*>(rpc+xs);
            }
            rd[seg*4]=vd.x; rd[seg*4+1]=vd.y; rd[seg*4+2]=vd.z; rd[seg*4+3]=vd.w;
            rc[seg*4]=vc.x; rc[seg*4+1]=vc.y; rc[seg*4+2]=vc.z; rc[seg*4+3]=vc.w;
        }
#pragma unroll
        for(int rx=0;rx<3;rx++){
            int k=ry*3+rx;
            float wk=w[k];
#pragma unroll
            for(int j=0;j<8;j++){
                float f=wk*e[emap[k]][j];
                md[j]+=f*rd[j+3+rx];
                mc[j]+=f*rc[j+3+rx];
            }
        }
    }
    float* shd=(float*)sh4;        // 2112 floats
    float* shc=shd+2112;
#pragma unroll
    for(int j=0;j<8;j++){ shd[(pg*8+j)*33+o]=md[j]; shc[(pg*8+j)*33+o]=mc[j]; }
    __syncthreads();

    // ---- phase D: 32x32 mix -> main outputs ----
    float ad[8],ac2[8];
#pragma unroll
    for(int j=0;j<8;j++){ ad[j]=0.f; ac2[j]=0.f; }
#pragma unroll 4
    for(int ii=0;ii<32;ii++){
        float wv=sh_wcdT[ii*32+o];
#pragma unroll
        for(int j=0;j<8;j++){
            ad[j]+=wv*shd[(pg*8+j)*33+ii];
            ac2[j]+=wv*shc[(pg*8+j)*33+ii];
        }
    }
    float* od=dout+(size_t)(b*32+o)*HW+y0*Ww+x0+pg*8;
    float* oc=dout+(size_t)(64+b*32+o)*HW+y0*Ww+x0+pg*8;
    *reinterpret_cast<float4*>(od)  =make_float4(ad[0],ad[1],ad[2],ad[3]);
    *reinterpret_cast<float4*>(od+4)=make_float4(ad[4],ad[5],ad[6],ad[7]);
    *reinterpret_cast<float4*>(oc)  =make_float4(ac2[0],ac2[1],ac2[2],ac2[3]);
    *reinterpret_cast<float4*>(oc+4)=make_float4(ac2[4],ac2[5],ac2[6],ac2[7]);
}

extern "C" void kernel_launch(void* const* d_in, const int* in_sizes, int n_in,
                              void* d_out, int out_size)
{
    const float* x   =(const float*)d_in[0];
    const float* ece =(const float*)d_in[1];
    const float* ce  =(const float*)d_in[2];
    static bool attr_done=false;
    if(!attr_done){
        cudaFuncSetAttribute(k23_fused, cudaFuncAttributeMaxDynamicSharedMemorySize, K23_SMEM);
        attr_done=true;
    }
    prep_kernel<<<1,160>>>((const float*)d_in[3],(const float*)d_in[4],
                           (const float*)d_in[5],(const float*)d_in[6],
                           (const float*)d_in[7],(const float*)d_in[8],
                           (const float*)d_in[9],(const float*)d_in[10],
                           (const float*)d_in[11]);
    k1_prepin<<<dim3(18,64),256>>>(x,ece,ce);
    k23_fused<<<1152,256,K23_SMEM>>>(x,(float*)d_out);
}

// round 5
// speedup vs baseline: 1.1958x; 1.1958x over previous
#include <cuda_runtime.h>
#include <math.h>

#define EPSV  1e-20f
#define L2EPS -66.438561897f
#define Hh 192
#define Ww 192
#define HW (Hh*Ww)

__device__ float g_wcd[1024];     // channel_d [o][i]
__device__ float g_wsd[288];      // spatial_d [i][k]
__device__ float g_wce[1024];     // channel_e [o][i]
__device__ float g_wdir[512];     // [p][i][d]
__device__ float g_wse[1152];     // [i][d][k]
__device__ float g_wprop[128];    // [i][d]
__device__ float g_wpow0[128];    // [i][d]
__device__ float g_wpow1[128];    // [i][d]
__device__ float g_cein [2*32*4*HW];
__device__ float g_ecein[2*32*4*HW];

__device__ __forceinline__ float sp_(float v){ return log1pf(expf(v)); }
__device__ __forceinline__ float sig_(float v){ return 1.f/(1.f+expf(-v)); }
__device__ __forceinline__ float ex2_(float v){
    float r; asm("ex2.approx.f32 %0, %1;" : "=f"(r) : "f"(v)); return r;
}
__device__ __forceinline__ float wsum_(float v){
#pragma unroll
    for(int m=16;m;m>>=1) v+=__shfl_xor_sync(0xffffffffu,v,m);
    return v;
}

// ---------------- prep: 5 blocks x 32 warps, warp=channel, lane=element ----------------
__global__ void prep_kernel(const float* __restrict__ Wcd, const float* __restrict__ Wsd,
                            const float* __restrict__ Wce, const float* __restrict__ Wse0,
                            const float* __restrict__ Wse1, const float* __restrict__ Wse3,
                            const float* __restrict__ Wdir, const float* __restrict__ Wpow,
                            const float* __restrict__ Wprop)
{
    int blk=blockIdx.x;
    int t=threadIdx.x>>5, lane=threadIdx.x&31;
    if(blk==0){
        float v=sp_(Wcd[t*32+lane]);
        float s=wsum_(v);
        g_wcd[t*32+lane]=v/s;
    } else if(blk==1){
        float v=sp_(Wce[t*32+lane]);
        float s=wsum_(v);
        g_wce[t*32+lane]=v/s;
    } else if(blk==2){ // spatial_d + prop + pow
        float v=0.f;
        if(lane<9) v=sp_(Wsd[t*6+(lane/3)*2+((lane%3)==1)]);
        float s=wsum_(v);
        if(lane<9) g_wsd[t*9+lane]=v/s;
        if(lane==0){
            float s0=sig_(Wprop[t*3+0]), s1=sig_(Wprop[t*3+1]), s2=sig_(Wprop[t*3+2]);
            g_wprop[t*4+0]=s1; g_wprop[t*4+1]=s0; g_wprop[t*4+2]=s1; g_wprop[t*4+3]=s2;
            float p0=sp_(Wpow[t*5+0]),p1=sp_(Wpow[t*5+1]),p2=sp_(Wpow[t*5+2]),
                  p3=sp_(Wpow[t*5+3]),p4=sp_(Wpow[t*5+4]);
            g_wpow0[t*4+0]=p0; g_wpow0[t*4+1]=p2; g_wpow0[t*4+2]=p1; g_wpow0[t*4+3]=p4;
            g_wpow1[t*4+0]=p1; g_wpow1[t*4+1]=p3; g_wpow1[t*4+2]=p0; g_wpow1[t*4+3]=p4;
        }
    } else if(blk==3){ // dir: lane = p*4+d
        const int map[16]={0,1,2,3, 4,5,4,6, 2,1,0,3, 7,8,7,9};
        float v=0.f;
        if(lane<16) v=sp_(Wdir[t*10+map[lane]]);
        float s=v;
        s+=__shfl_xor_sync(0xffffffffu,s,1);
        s+=__shfl_xor_sync(0xffffffffu,s,2);
        if(lane<16) g_wdir[((lane>>2)*32+t)*4+(lane&3)]=v/s;
    } else { // spatial_e
        float v0=0.f,v1=0.f,v2=0.f,v3=0.f;
        if(lane<9){
            int h=lane/3,c=lane%3;
            v0=sp_(Wse0[t*9+lane]);
            v1=sp_(Wse1[t*6+h*2+(c==1)]);
            v2=sp_(Wse0[t*9+h*3+(2-c)]);
            v3=sp_(Wse3[t*6+h*2+(c==1)]);
        }
        float s0=wsum_(v0), s1=wsum_(v1), s2=wsum_(v2), s3=wsum_(v3);
        if(lane<9){
            g_wse[(t*4+0)*9+lane]=v0/s0;
            g_wse[(t*4+1)*9+lane]=v1/s1;
            g_wse[(t*4+2)*9+lane]=v2/s2;
            g_wse[(t*4+3)*9+lane]=v3/s3;
        }
    }
}

// ---------------- K1: vectorized, 8 px/thread ----------------
__global__ void __launch_bounds__(256) k1_prepin(const float* __restrict__ x,
                                                 const float* __restrict__ ece,
                                                 const float* __restrict__ ce)
{
    int plane = blockIdx.y;                 // b*32+i, 0..63
    int i = plane & 31;
    int g = blockIdx.x*256 + threadIdx.x;   // 18*256 = 4608
    int y = g/24, xg = (g - y*24)*8;
    const float* dcd = x + (size_t)plane*HW;
    const float* cdp = x + (size_t)(64+plane)*HW;

    float lv[3][10], cv[3][10];
#pragma unroll
    for(int r=0;r<3;r++){
        int yy=y-1+r;
        bool yok=((unsigned)yy<(unsigned)Hh);
        const float* rd0=dcd+yy*Ww;
        const float* rc0=cdp+yy*Ww;
        float rd[16],rc[16];
#pragma unroll
        for(int seg=0;seg<4;seg++){
            int xs=xg-4+seg*4;
            float4 vd=make_float4(0.f,0.f,0.f,0.f), vc=vd;
            if(yok&&(unsigned)xs<(unsigned)Ww){
                vd=*reinterpret_cast<const float4*>(rd0+xs);
                vc=*reinterpret_cast<const float4*>(rc0+xs);
            }
            rd[seg*4]=vd.x; rd[seg*4+1]=vd.y; rd[seg*4+2]=vd.z; rd[seg*4+3]=vd.w;
            rc[seg*4]=vc.x; rc[seg*4+1]=vc.y; rc[seg*4+2]=vc.z; rc[seg*4+3]=vc.w;
        }
#pragma unroll
        for(int idx=0;idx<10;idx++){
            float dc=rd[idx+3], c=rc[idx+3];
            cv[r][idx]=c;
            float l=__log2f(dc)-__log2f(c+EPSV);
            lv[r][idx]=(dc>0.f)? l : -1e30f;
        }
    }
    const int Ar[4]={0,0,0,1}, Ac[4]={0,1,2,2};
    const int Br[4]={2,2,2,1}, Bc[4]={2,1,0,0};
    size_t base=(size_t)plane*4*HW + y*Ww + xg;
#pragma unroll
    for(int d=0;d<4;d++){
        float p0=g_wpow0[i*4+d], p1=g_wpow1[i*4+d], wp=g_wprop[i*4+d];
        size_t off=base+(size_t)d*HW;
        float4 cea=*reinterpret_cast<const float4*>(ce+off);
        float4 ceb=*reinterpret_cast<const float4*>(ce+off+4);
        float4 eca=*reinterpret_cast<const float4*>(ece+off);
        float4 ecb=*reinterpret_cast<const float4*>(ece+off+4);
        float cei[8]={cea.x,cea.y,cea.z,cea.w,ceb.x,ceb.y,ceb.z,ceb.w};
        float eci[8]={eca.x,eca.y,eca.z,eca.w,ecb.x,ecb.y,ecb.z,ecb.w};
        float oc[8],oe[8];
#pragma unroll
        for(int j=0;j<8;j++){
            float lA=lv[Ar[d]][j+Ac[d]], lB=lv[Br[d]][j+Bc[d]];
            float la=fminf(fmaxf(lA-fmaxf(lB,L2EPS),L2EPS),0.f);
            float lb=fminf(fmaxf(lB-fmaxf(lA,L2EPS),L2EPS),0.f);
            float en=ex2_(fminf(p0*la,p1*lb));
            float cn=cv[Ar[d]][j+Ac[d]]*cv[Br[d]][j+Bc[d]];
            oc[j]=cei[j]*wp+cn*(1.f-wp);
            oe[j]=eci[j]*wp+en*cn*(1.f-wp);
        }
        *reinterpret_cast<float4*>(g_cein+off)   =make_float4(oc[0],oc[1],oc[2],oc[3]);
        *reinterpret_cast<float4*>(g_cein+off+4) =make_float4(oc[4],oc[5],oc[6],oc[7]);
        *reinterpret_cast<float4*>(g_ecein+off)  =make_float4(oe[0],oe[1],oe[2],oe[3]);
        *reinterpret_cast<float4*>(g_ecein+off+4)=make_float4(oe[4],oe[5],oe[6],oe[7]);
    }
}

// K2: factorized conv_e: depthwise 3x3 -> 4x4 dir mix -> 32x32 channel mix
__global__ void __launch_bounds__(256) k2_conve(float* __restrict__ dout)
{
    __shared__ float4 sh4[64][33];
    __shared__ float sh_wse[1152];
    __shared__ float sh_wdir[512];
    __shared__ float sh_wceT[1024];
    int tid=threadIdx.x;
    for(int k=tid;k<1152;k+=256) sh_wse[k]=g_wse[k];
    for(int k=tid;k<512;k+=256)  sh_wdir[k]=g_wdir[k];
    for(int k=tid;k<1024;k+=256) sh_wceT[k]=g_wce[(k&31)*32+(k>>5)];
    int t=blockIdx.x;
    int b=t/576; int rem=t-b*576;
    int y0=rem/3; int x0=(rem-y0*3)*64;
    int i=tid>>3, px8=tid&7;
    int xb=x0+px8*8;
    int o=tid&31, pg=tid>>5;
    __syncthreads();

    const size_t ece_off=(size_t)128*HW;
    const size_t ceo_off=(size_t)384*HW;

    for(int sel=0;sel<2;sel++){
        const float* __restrict__ in = sel ? g_ecein : g_cein;
        float tacc[4][8];
#pragma unroll
        for(int p=0;p<4;p++)
#pragma unroll
            for(int j=0;j<8;j++) tacc[p][j]=0.f;
#pragma unroll
        for(int d=0;d<4;d++){
            const float* ch = in + (size_t)((b*32+i)*4+d)*HW;
            const float* w = sh_wse + (i*4+d)*9;
            float s[8];
#pragma unroll
            for(int j=0;j<8;j++) s[j]=0.f;
#pragma unroll
            for(int ry=0;ry<3;ry++){
                int yy=y0+ry-1;
                bool yok=((unsigned)yy<(unsigned)Hh);
                const float* rp=ch+yy*Ww;
                float r[16];
#pragma unroll
                for(int seg=0;seg<4;seg++){
                    int xs=xb-4+seg*4;
                    float4 v=make_float4(0.f,0.f,0.f,0.f);
                    if(yok&&(unsigned)xs<(unsigned)Ww)
                        v=*reinterpret_cast<const float4*>(rp+xs);
                    r[seg*4]=v.x; r[seg*4+1]=v.y; r[seg*4+2]=v.z; r[seg*4+3]=v.w;
                }
                float w0=w[ry*3],w1=w[ry*3+1],w2=w[ry*3+2];
#pragma unroll
                for(int j=0;j<8;j++)
                    s[j]+=w0*r[j+3]+w1*r[j+4]+w2*r[j+5];
            }
#pragma unroll
            for(int p=0;p<4;p++){
                float wd=sh_wdir[(p*32+i)*4+d];
#pragma unroll
                for(int j=0;j<8;j++) tacc[p][j]+=wd*s[j];
            }
        }
#pragma unroll
        for(int j=0;j<8;j++)
            sh4[px8*8+j][i]=make_float4(tacc[0][j],tacc[1][j],tacc[2][j],tacc[3][j]);
        __syncthreads();

        float acc[4][8];
#pragma unroll
        for(int p=0;p<4;p++)
#pragma unroll
            for(int j=0;j<8;j++) acc[p][j]=0.f;
#pragma unroll 4
        for(int ii=0;ii<32;ii++){
            float wv=sh_wceT[ii*32+o];
#pragma unroll
            for(int j=0;j<8;j++){
                float4 tv=sh4[pg*8+j][ii];
                acc[0][j]+=wv*tv.x; acc[1][j]+=wv*tv.y;
                acc[2][j]+=wv*tv.z; acc[3][j]+=wv*tv.w;
            }
        }
        size_t ooff = sel ? ece_off : ceo_off;
#pragma unroll
        for(int p=0;p<4;p++){
            float* op=dout+ooff+(size_t)((b*32+o)*4+p)*HW+y0*Ww+x0+pg*8;
            *reinterpret_cast<float4*>(op)  =make_float4(acc[p][0],acc[p][1],acc[p][2],acc[p][3]);
            *reinterpret_cast<float4*>(op+4)=make_float4(acc[p][4],acc[p][5],acc[p][6],acc[p][7]);
        }
        __syncthreads();
    }
}

// K3: e9-modulated depthwise + 32x32 mix -> main output
__global__ void __launch_bounds__(256) k3_final(const float* __restrict__ x,
                                                float* __restrict__ dout)
{
    __shared__ float shd[64][33];
    __shared__ float shc[64][33];
    __shared__ float sh_wcdT[1024];
    __shared__ float sh_wsd[288];
    int tid=threadIdx.x;
    for(int k=tid;k<1024;k+=256) sh_wcdT[k]=g_wcd[(k&31)*32+(k>>5)];
    for(int k=tid;k<288;k+=256)  sh_wsd[k]=g_wsd[k];
    int t=blockIdx.x;
    int b=t/576; int rem=t-b*576;
    int y0=rem/3; int x0=(rem-y0*3)*64;
    int i=tid>>3, px8=tid&7;
    int xb=x0+px8*8;
    int o=tid&31, pg=tid>>5;
    __syncthreads();

    const size_t ece_off=(size_t)128*HW;
    const size_t ceo_off=(size_t)384*HW;
    float e[5][8];
#pragma unroll
    for(int j=0;j<8;j++) e[4][j]=1.f;
    size_t pbase=(size_t)(b*32+i)*4*HW + y0*Ww + xb;
#pragma unroll
    for(int d=0;d<4;d++){
        const float* pe=dout+ece_off+pbase+(size_t)d*HW;
        const float* pc=dout+ceo_off+pbase+(size_t)d*HW;
#pragma unroll
        for(int j=0;j<8;j+=4){
            float4 ev=*reinterpret_cast<const float4*>(pe+j);
            float4 c4=*reinterpret_cast<const float4*>(pc+j);
            e[d][j]  =fminf(fmaxf(__fdividef(ev.x,c4.x+EPSV),EPSV),1.f);
            e[d][j+1]=fminf(fmaxf(__fdividef(ev.y,c4.y+EPSV),EPSV),1.f);
            e[d][j+2]=fminf(fmaxf(__fdividef(ev.z,c4.z+EPSV),EPSV),1.f);
            e[d][j+3]=fminf(fmaxf(__fdividef(ev.w,c4.w+EPSV),EPSV),1.f);
        }
    }
    const float* dcd=x+(size_t)(b*32+i)*HW;
    const float* cdp=x+(size_t)(64+b*32+i)*HW;
    const float* w=sh_wsd+i*9;
    float md[8],mc[8];
#pragma unroll
    for(int j=0;j<8;j++){ md[j]=0.f; mc[j]=0.f; }
    const int emap[9]={0,1,2,3,4,3,2,1,0};
#pragma unroll
    for(int ry=0;ry<3;ry++){
        int yy=y0+ry-1;
        bool yok=((unsigned)yy<(unsigned)Hh);
        const float* rpd=dcd+yy*Ww;
        const float* rpc=cdp+yy*Ww;
        float rd[16],rc[16];
#pragma unroll
        for(int seg=0;seg<4;seg++){
            int xs=xb-4+seg*4;
            float4 vd=make_float4(0.f,0.f,0.f,0.f), vc=vd;
            if(yok&&(unsigned)xs<(unsigned)Ww){
                vd=*reinterpret_cast<const float4*>(rpd+xs);
                vc=*reinterpret_cast<const float4*>(rpc+xs);
            }
            rd[seg*4]=vd.x; rd[seg*4+1]=vd.y; rd[seg*4+2]=vd.z; rd[seg*4+3]=vd.w;
            rc[seg*4]=vc.x; rc[seg*4+1]=vc.y; rc[seg*4+2]=vc.z; rc[seg*4+3]=vc.w;
        }
#pragma unroll
        for(int rx=0;rx<3;rx++){
            int k=ry*3+rx;
            float wk=w[k];
#pragma unroll
            for(int j=0;j<8;j++){
                float f=wk*e[emap[k]][j];
                md[j]+=f*rd[j+3+rx];
                mc[j]+=f*rc[j+3+rx];
            }
        }
    }
#pragma unroll
    for(int j=0;j<8;j++){ shd[px8*8+j][i]=md[j]; shc[px8*8+j][i]=mc[j]; }
    __syncthreads();
    float ad[8],ac[8];
#pragma unroll
    for(int j=0;j<8;j++){ ad[j]=0.f; ac[j]=0.f; }
#pragma unroll 4
    for(int ii=0;ii<32;ii++){
        float wv=sh_wcdT[ii*32+o];
#pragma unroll
        for(int j=0;j<8;j++){
            ad[j]+=wv*shd[pg*8+j][ii];
            ac[j]+=wv*shc[pg*8+j][ii];
        }
    }
    float* od=dout+(size_t)(b*32+o)*HW+y0*Ww+x0+pg*8;
    float* oc=dout+(size_t)(64+b*32+o)*HW+y0*Ww+x0+pg*8;
    *reinterpret_cast<float4*>(od)  =make_float4(ad[0],ad[1],ad[2],ad[3]);
    *reinterpret_cast<float4*>(od+4)=make_float4(ad[4],ad[5],ad[6],ad[7]);
    *reinterpret_cast<float4*>(oc)  =make_float4(ac[0],ac[1],ac[2],ac[3]);
    *reinterpret_cast<float4*>(oc+4)=make_float4(ac[4],ac[5],ac[6],ac[7]);
}

extern "C" void kernel_launch(void* const* d_in, const int* in_sizes, int n_in,
                              void* d_out, int out_size)
{
    const float* x   =(const float*)d_in[0];
    const float* ece =(const float*)d_in[1];
    const float* ce  =(const float*)d_in[2];
    prep_kernel<<<5,1024>>>((const float*)d_in[3],(const float*)d_in[4],
                            (const float*)d_in[5],(const float*)d_in[6],
                            (const float*)d_in[7],(const float*)d_in[8],
                            (const float*)d_in[9],(const float*)d_in[10],
                            (const float*)d_in[11]);
    k1_prepin<<<dim3(18,64),256>>>(x,ece,ce);
    k2_conve<<<1152,256>>>((float*)d_out);
    k3_final<<<1152,256>>>(x,(float*)d_out);
}

// round 6
// speedup vs baseline: 1.2440x; 1.0403x over previous
#include <cuda_runtime.h>
#include <math.h>

#define EPSV  1e-20f
#define L2EPS -66.438561897f
#define Hh 192
#define Ww 192
#define HW (Hh*Ww)

__device__ float g_wcd[1024];     // channel_d [o][i]
__device__ float g_wsd[288];      // spatial_d [i][k]
__device__ float g_wce[1024];     // channel_e [o][i]
__device__ float g_wdir[512];     // [p][i][d]
__device__ float g_wse[1152];     // [i][d][k]
__device__ float g_wprop[128];    // [i][d]
__device__ float g_wpow0[128];    // [i][d]
__device__ float g_wpow1[128];    // [i][d]
__device__ float g_cein [2*32*4*HW];
__device__ float g_ecein[2*32*4*HW];

__device__ __forceinline__ float sp_(float v){ return log1pf(expf(v)); }
__device__ __forceinline__ float sig_(float v){ return 1.f/(1.f+expf(-v)); }
__device__ __forceinline__ float ex2_(float v){
    float r; asm("ex2.approx.f32 %0, %1;" : "=f"(r) : "f"(v)); return r;
}
__device__ __forceinline__ float wsum_(float v){
#pragma unroll
    for(int m=16;m;m>>=1) v+=__shfl_xor_sync(0xffffffffu,v,m);
    return v;
}

// ---------------- prep: 5 blocks x 32 warps ----------------
__global__ void prep_kernel(const float* __restrict__ Wcd, const float* __restrict__ Wsd,
                            const float* __restrict__ Wce, const float* __restrict__ Wse0,
                            const float* __restrict__ Wse1, const float* __restrict__ Wse3,
                            const float* __restrict__ Wdir, const float* __restrict__ Wpow,
                            const float* __restrict__ Wprop)
{
    int blk=blockIdx.x;
    int t=threadIdx.x>>5, lane=threadIdx.x&31;
    if(blk==0){
        float v=sp_(Wcd[t*32+lane]);
        float s=wsum_(v);
        g_wcd[t*32+lane]=v/s;
    } else if(blk==1){
        float v=sp_(Wce[t*32+lane]);
        float s=wsum_(v);
        g_wce[t*32+lane]=v/s;
    } else if(blk==2){
        float v=0.f;
        if(lane<9) v=sp_(Wsd[t*6+(lane/3)*2+((lane%3)==1)]);
        float s=wsum_(v);
        if(lane<9) g_wsd[t*9+lane]=v/s;
        if(lane==0){
            float s0=sig_(Wprop[t*3+0]), s1=sig_(Wprop[t*3+1]), s2=sig_(Wprop[t*3+2]);
            g_wprop[t*4+0]=s1; g_wprop[t*4+1]=s0; g_wprop[t*4+2]=s1; g_wprop[t*4+3]=s2;
            float p0=sp_(Wpow[t*5+0]),p1=sp_(Wpow[t*5+1]),p2=sp_(Wpow[t*5+2]),
                  p3=sp_(Wpow[t*5+3]),p4=sp_(Wpow[t*5+4]);
            g_wpow0[t*4+0]=p0; g_wpow0[t*4+1]=p2; g_wpow0[t*4+2]=p1; g_wpow0[t*4+3]=p4;
            g_wpow1[t*4+0]=p1; g_wpow1[t*4+1]=p3; g_wpow1[t*4+2]=p0; g_wpow1[t*4+3]=p4;
        }
    } else if(blk==3){
        const int map[16]={0,1,2,3, 4,5,4,6, 2,1,0,3, 7,8,7,9};
        float v=0.f;
        if(lane<16) v=sp_(Wdir[t*10+map[lane]]);
        float s=v;
        s+=__shfl_xor_sync(0xffffffffu,s,1);
        s+=__shfl_xor_sync(0xffffffffu,s,2);
        if(lane<16) g_wdir[((lane>>2)*32+t)*4+(lane&3)]=v/s;
    } else {
        float v0=0.f,v1=0.f,v2=0.f,v3=0.f;
        if(lane<9){
            int h=lane/3,c=lane%3;
            v0=sp_(Wse0[t*9+lane]);
            v1=sp_(Wse1[t*6+h*2+(c==1)]);
            v2=sp_(Wse0[t*9+h*3+(2-c)]);
            v3=sp_(Wse3[t*6+h*2+(c==1)]);
        }
        float s0=wsum_(v0), s1=wsum_(v1), s2=wsum_(v2), s3=wsum_(v3);
        if(lane<9){
            g_wse[(t*4+0)*9+lane]=v0/s0;
            g_wse[(t*4+1)*9+lane]=v1/s1;
            g_wse[(t*4+2)*9+lane]=v2/s2;
            g_wse[(t*4+3)*9+lane]=v3/s3;
        }
    }
}

// ---------------- K1: vectorized, 8 px/thread ----------------
__global__ void __launch_bounds__(256) k1_prepin(const float* __restrict__ x,
                                                 const float* __restrict__ ece,
                                                 const float* __restrict__ ce)
{
    int plane = blockIdx.y;
    int i = plane & 31;
    int g = blockIdx.x*256 + threadIdx.x;
    int y = g/24, xg = (g - y*24)*8;
    const float* dcd = x + (size_t)plane*HW;
    const float* cdp = x + (size_t)(64+plane)*HW;

    float lv[3][10], cv[3][10];
#pragma unroll
    for(int r=0;r<3;r++){
        int yy=y-1+r;
        bool yok=((unsigned)yy<(unsigned)Hh);
        const float* rd0=dcd+yy*Ww;
        const float* rc0=cdp+yy*Ww;
        float rd[16],rc[16];
#pragma unroll
        for(int seg=0;seg<4;seg++){
            int xs=xg-4+seg*4;
            float4 vd=make_float4(0.f,0.f,0.f,0.f), vc=vd;
            if(yok&&(unsigned)xs<(unsigned)Ww){
                vd=*reinterpret_cast<const float4*>(rd0+xs);
                vc=*reinterpret_cast<const float4*>(rc0+xs);
            }
            rd[seg*4]=vd.x; rd[seg*4+1]=vd.y; rd[seg*4+2]=vd.z; rd[seg*4+3]=vd.w;
            rc[seg*4]=vc.x; rc[seg*4+1]=vc.y; rc[seg*4+2]=vc.z; rc[seg*4+3]=vc.w;
        }
#pragma unroll
        for(int idx=0;idx<10;idx++){
            float dc=rd[idx+3], c=rc[idx+3];
            cv[r][idx]=c;
            float l=__log2f(dc)-__log2f(c+EPSV);
            lv[r][idx]=(dc>0.f)? l : -1e30f;
        }
    }
    const int Ar[4]={0,0,0,1}, Ac[4]={0,1,2,2};
    const int Br[4]={2,2,2,1}, Bc[4]={2,1,0,0};
    size_t base=(size_t)plane*4*HW + y*Ww + xg;
#pragma unroll
    for(int d=0;d<4;d++){
        float p0=g_wpow0[i*4+d], p1=g_wpow1[i*4+d], wp=g_wprop[i*4+d];
        size_t off=base+(size_t)d*HW;
        float4 cea=*reinterpret_cast<const float4*>(ce+off);
        float4 ceb=*reinterpret_cast<const float4*>(ce+off+4);
        float4 eca=*reinterpret_cast<const float4*>(ece+off);
        float4 ecb=*reinterpret_cast<const float4*>(ece+off+4);
        float cei[8]={cea.x,cea.y,cea.z,cea.w,ceb.x,ceb.y,ceb.z,ceb.w};
        float eci[8]={eca.x,eca.y,eca.z,eca.w,ecb.x,ecb.y,ecb.z,ecb.w};
        float oc[8],oe[8];
#pragma unroll
        for(int j=0;j<8;j++){
            float lA=lv[Ar[d]][j+Ac[d]], lB=lv[Br[d]][j+Bc[d]];
            float la=fminf(fmaxf(lA-fmaxf(lB,L2EPS),L2EPS),0.f);
            float lb=fminf(fmaxf(lB-fmaxf(lA,L2EPS),L2EPS),0.f);
            float en=ex2_(fminf(p0*la,p1*lb));
            float cn=cv[Ar[d]][j+Ac[d]]*cv[Br[d]][j+Bc[d]];
            oc[j]=cei[j]*wp+cn*(1.f-wp);
            oe[j]=eci[j]*wp+en*cn*(1.f-wp);
        }
        *reinterpret_cast<float4*>(g_cein+off)   =make_float4(oc[0],oc[1],oc[2],oc[3]);
        *reinterpret_cast<float4*>(g_cein+off+4) =make_float4(oc[4],oc[5],oc[6],oc[7]);
        *reinterpret_cast<float4*>(g_ecein+off)  =make_float4(oe[0],oe[1],oe[2],oe[3]);
        *reinterpret_cast<float4*>(g_ecein+off+4)=make_float4(oe[4],oe[5],oe[6],oe[7]);
    }
}

// ---------------- K2: shuffle-halo loads + o-pair phase B ----------------
__global__ void __launch_bounds__(256,3) k2_conve(float* __restrict__ dout)
{
    __shared__ float4 sh4[64][33];
    __shared__ float sh_wse[1152];
    __shared__ float sh_wdir[512];
    __shared__ float sh_wceT[1024];
    int tid=threadIdx.x;
    for(int k=tid;k<1152;k+=256) sh_wse[k]=g_wse[k];
    for(int k=tid;k<512;k+=256)  sh_wdir[k]=g_wdir[k];
    for(int k=tid;k<1024;k+=256) sh_wceT[k]=g_wce[(k&31)*32+(k>>5)];
    int t=blockIdx.x;
    int b=t/576; int rem=t-b*576;
    int y0=rem/3; int x0=(rem-y0*3)*64;
    int i=tid>>3, px8=tid&7;
    int xb=x0+px8*8;
    int ob=tid&15, pxg=tid>>4;
    __syncthreads();

    const size_t ece_off=(size_t)128*HW;
    const size_t ceo_off=(size_t)384*HW;

    for(int sel=0;sel<2;sel++){
        const float* __restrict__ in = sel ? g_ecein : g_cein;
        float tacc[4][8];
#pragma unroll
        for(int p=0;p<4;p++)
#pragma unroll
            for(int j=0;j<8;j++) tacc[p][j]=0.f;
#pragma unroll
        for(int d=0;d<4;d++){
            const float* ch = in + (size_t)((b*32+i)*4+d)*HW;
            const float* w = sh_wse + (i*4+d)*9;
            float s[8];
#pragma unroll
            for(int j=0;j<8;j++) s[j]=0.f;
#pragma unroll
            for(int ry=0;ry<3;ry++){
                int yy=y0+ry-1;
                bool yok=((unsigned)yy<(unsigned)Hh);
                const float* rp=ch+yy*Ww;
                float4 a=make_float4(0.f,0.f,0.f,0.f), bb=a;
                if(yok){
                    a =*reinterpret_cast<const float4*>(rp+xb);
                    bb=*reinterpret_cast<const float4*>(rp+xb+4);
                }
                float lf=__shfl_up_sync(0xffffffffu,bb.w,1);
                float rt=__shfl_down_sync(0xffffffffu,a.x,1);
                if(px8==0) lf=(yok&&xb>0)       ? rp[xb-1] : 0.f;
                if(px8==7) rt=(yok&&(xb+8)<Ww)  ? rp[xb+8] : 0.f;
                float r[10]={lf,a.x,a.y,a.z,a.w,bb.x,bb.y,bb.z,bb.w,rt};
                float w0=w[ry*3],w1=w[ry*3+1],w2=w[ry*3+2];
#pragma unroll
                for(int j=0;j<8;j++)
                    s[j]+=w0*r[j]+w1*r[j+1]+w2*r[j+2];
            }
#pragma unroll
            for(int p=0;p<4;p++){
                float wd=sh_wdir[(p*32+i)*4+d];
#pragma unroll
                for(int j=0;j<8;j++) tacc[p][j]+=wd*s[j];
            }
        }
#pragma unroll
        for(int j=0;j<8;j++)
            sh4[px8*8+j][i]=make_float4(tacc[0][j],tacc[1][j],tacc[2][j],tacc[3][j]);
        __syncthreads();

        // phase B: o-pair (ob, ob+16) x 4 px
        float4 accA[4],accB[4];
#pragma unroll
        for(int l=0;l<4;l++){
            accA[l]=make_float4(0.f,0.f,0.f,0.f);
            accB[l]=make_float4(0.f,0.f,0.f,0.f);
        }
#pragma unroll 4
        for(int ii=0;ii<32;ii++){
            float wA=sh_wceT[ii*32+ob];
            float wB=sh_wceT[ii*32+ob+16];
#pragma unroll
            for(int l=0;l<4;l++){
                float4 tv=sh4[pxg*4+l][ii];
                accA[l].x+=wA*tv.x; accA[l].y+=wA*tv.y; accA[l].z+=wA*tv.z; accA[l].w+=wA*tv.w;
                accB[l].x+=wB*tv.x; accB[l].y+=wB*tv.y; accB[l].z+=wB*tv.z; accB[l].w+=wB*tv.w;
            }
        }
        size_t ooff = sel ? ece_off : ceo_off;
        {
            float* baseA=dout+ooff+(size_t)((b*32+ob)*4)*HW+y0*Ww+x0+pxg*4;
            float* baseB=dout+ooff+(size_t)((b*32+ob+16)*4)*HW+y0*Ww+x0+pxg*4;
            *reinterpret_cast<float4*>(baseA)       =make_float4(accA[0].x,accA[1].x,accA[2].x,accA[3].x);
            *reinterpret_cast<float4*>(baseA+HW)    =make_float4(accA[0].y,accA[1].y,accA[2].y,accA[3].y);
            *reinterpret_cast<float4*>(baseA+2*HW)  =make_float4(accA[0].z,accA[1].z,accA[2].z,accA[3].z);
            *reinterpret_cast<float4*>(baseA+3*HW)  =make_float4(accA[0].w,accA[1].w,accA[2].w,accA[3].w);
            *reinterpret_cast<float4*>(baseB)       =make_float4(accB[0].x,accB[1].x,accB[2].x,accB[3].x);
            *reinterpret_cast<float4*>(baseB+HW)    =make_float4(accB[0].y,accB[1].y,accB[2].y,accB[3].y);
            *reinterpret_cast<float4*>(baseB+2*HW)  =make_float4(accB[0].z,accB[1].z,accB[2].z,accB[3].z);
            *reinterpret_cast<float4*>(baseB+3*HW)  =make_float4(accB[0].w,accB[1].w,accB[2].w,accB[3].w);
        }
        __syncthreads();
    }
}

// ---------------- K3: 512 threads, 4 px/thread, shuffle-halo ----------------
__global__ void __launch_bounds__(512,2) k3_final(const float* __restrict__ x,
                                                  float* __restrict__ dout)
{
    __shared__ float2 sh2[64][33];
    __shared__ float sh_wcdT[1024];
    __shared__ float sh_wsd[288];
    int tid=threadIdx.x;
    for(int k=tid;k<1024;k+=512) sh_wcdT[k]=g_wcd[(k&31)*32+(k>>5)];
    for(int k=tid;k<288;k+=512)  sh_wsd[k]=g_wsd[k];
    int t=blockIdx.x;
    int b=t/576; int rem=t-b*576;
    int y0=rem/3; int x0=(rem-y0*3)*64;
    int i=tid>>4, pxg=tid&15;
    int xb=x0+pxg*4;
    int o=tid&31, pxg2=tid>>5;   // 0..15
    __syncthreads();

    const size_t ece_off=(size_t)128*HW;
    const size_t ceo_off=(size_t)384*HW;
    float e[5][4];
#pragma unroll
    for(int j=0;j<4;j++) e[4][j]=1.f;
    size_t pbase=(size_t)(b*32+i)*4*HW + y0*Ww + xb;
#pragma unroll
    for(int d=0;d<4;d++){
        float4 ev=*reinterpret_cast<const float4*>(dout+ece_off+pbase+(size_t)d*HW);
        float4 c4=*reinterpret_cast<const float4*>(dout+ceo_off+pbase+(size_t)d*HW);
        e[d][0]=fminf(fmaxf(__fdividef(ev.x,c4.x+EPSV),EPSV),1.f);
        e[d][1]=fminf(fmaxf(__fdividef(ev.y,c4.y+EPSV),EPSV),1.f);
        e[d][2]=fminf(fmaxf(__fdividef(ev.z,c4.z+EPSV),EPSV),1.f);
        e[d][3]=fminf(fmaxf(__fdividef(ev.w,c4.w+EPSV),EPSV),1.f);
    }
    const float* dcd=x+(size_t)(b*32+i)*HW;
    const float* cdp=x+(size_t)(64+b*32+i)*HW;
    const float* w=sh_wsd+i*9;
    float md[4]={0.f,0.f,0.f,0.f}, mc[4]={0.f,0.f,0.f,0.f};
    const int emap[9]={0,1,2,3,4,3,2,1,0};
#pragma unroll
    for(int ry=0;ry<3;ry++){
        int yy=y0+ry-1;
        bool yok=((unsigned)yy<(unsigned)Hh);
        const float* rpd=dcd+yy*Ww;
        const float* rpc=cdp+yy*Ww;
        float4 ad=make_float4(0.f,0.f,0.f,0.f), ac=ad;
        if(yok){
            ad=*reinterpret_cast<const float4*>(rpd+xb);
            ac=*reinterpret_cast<const float4*>(rpc+xb);
        }
        float lfd=__shfl_up_sync(0xffffffffu,ad.w,1);
        float lfc=__shfl_up_sync(0xffffffffu,ac.w,1);
        float rtd=__shfl_down_sync(0xffffffffu,ad.x,1);
        float rtc=__shfl_down_sync(0xffffffffu,ac.x,1);
        if(pxg==0){
            lfd=(yok&&xb>0)? rpd[xb-1]:0.f;
            lfc=(yok&&xb>0)? rpc[xb-1]:0.f;
        }
        if(pxg==15){
            rtd=(yok&&(xb+4)<Ww)? rpd[xb+4]:0.f;
            rtc=(yok&&(xb+4)<Ww)? rpc[xb+4]:0.f;
        }
        float rd[6]={lfd,ad.x,ad.y,ad.z,ad.w,rtd};
        float rc[6]={lfc,ac.x,ac.y,ac.z,ac.w,rtc};
#pragma unroll
        for(int rx=0;rx<3;rx++){
            int k=ry*3+rx;
            float wk=w[k];
#pragma unroll
            for(int j=0;j<4;j++){
                float f=wk*e[emap[k]][j];
                md[j]+=f*rd[j+rx];
                mc[j]+=f*rc[j+rx];
            }
        }
    }
#pragma unroll
    for(int j=0;j<4;j++) sh2[pxg*4+j][i]=make_float2(md[j],mc[j]);
    __syncthreads();
    float ad2[4]={0.f,0.f,0.f,0.f}, ac2[4]={0.f,0.f,0.f,0.f};
#pragma unroll 4
    for(int ii=0;ii<32;ii++){
        float wv=sh_wcdT[ii*32+o];
#pragma unroll
        for(int j=0;j<4;j++){
            float2 v=sh2[pxg2*4+j][ii];
            ad2[j]+=wv*v.x;
            ac2[j]+=wv*v.y;
        }
    }
    float* od=dout+(size_t)(b*32+o)*HW+y0*Ww+x0+pxg2*4;
    float* oc=dout+(size_t)(64+b*32+o)*HW+y0*Ww+x0+pxg2*4;
    *reinterpret_cast<float4*>(od)=make_float4(ad2[0],ad2[1],ad2[2],ad2[3]);
    *reinterpret_cast<float4*>(oc)=make_float4(ac2[0],ac2[1],ac2[2],ac2[3]);
}

extern "C" void kernel_launch(void* const* d_in, const int* in_sizes, int n_in,
                              void* d_out, int out_size)
{
    const float* x   =(const float*)d_in[0];
    const float* ece =(const float*)d_in[1];
    const float* ce  =(const float*)d_in[2];
    prep_kernel<<<5,1024>>>((const float*)d_in[3],(const float*)d_in[4],
                            (const float*)d_in[5],(const float*)d_in[6],
                            (const float*)d_in[7],(const float*)d_in[8],
                            (const float*)d_in[9],(const float*)d_in[10],
                            (const float*)d_in[11]);
    k1_prepin<<<dim3(18,64),256>>>(x,ece,ce);
    k2_conve<<<1152,256>>>((float*)d_out);
    k3_final<<<1152,512>>>(x,(float*)d_out);
}

// round 7
// speedup vs baseline: 1.2565x; 1.0100x over previous
#include <cuda_runtime.h>
#include <math.h>

#define EPSV  1e-20f
#define L2EPS -66.438561897f
#define Hh 192
#define Ww 192
#define HW (Hh*Ww)

__device__ float g_wcd[1024];     // channel_d [o][i]
__device__ float g_wsd[288];      // spatial_d [i][k]
__device__ float g_wce[1024];     // channel_e [o][i]
__device__ float g_wdir[512];     // [p][i][d]
__device__ float g_wse[1152];     // [i][d][k]
__device__ float g_wprop[128];    // [i][d]
__device__ float g_wpow0[128];    // [i][d]
__device__ float g_wpow1[128];    // [i][d]
__device__ float g_cein [2*32*4*HW];
__device__ float g_ecein[2*32*4*HW];

__device__ __forceinline__ float sp_(float v){ return log1pf(expf(v)); }
__device__ __forceinline__ float sig_(float v){ return 1.f/(1.f+expf(-v)); }
__device__ __forceinline__ float ex2_(float v){
    float r; asm("ex2.approx.f32 %0, %1;" : "=f"(r) : "f"(v)); return r;
}
__device__ __forceinline__ float wsum_(float v){
#pragma unroll
    for(int m=16;m;m>>=1) v+=__shfl_xor_sync(0xffffffffu,v,m);
    return v;
}

// ---------------- prep: 5 blocks x 32 warps ----------------
__global__ void prep_kernel(const float* __restrict__ Wcd, const float* __restrict__ Wsd,
                            const float* __restrict__ Wce, const float* __restrict__ Wse0,
                            const float* __restrict__ Wse1, const float* __restrict__ Wse3,
                            const float* __restrict__ Wdir, const float* __restrict__ Wpow,
                            const float* __restrict__ Wprop)
{
    int blk=blockIdx.x;
    int t=threadIdx.x>>5, lane=threadIdx.x&31;
    if(blk==0){
        float v=sp_(Wcd[t*32+lane]);
        float s=wsum_(v);
        g_wcd[t*32+lane]=v/s;
    } else if(blk==1){
        float v=sp_(Wce[t*32+lane]);
        float s=wsum_(v);
        g_wce[t*32+lane]=v/s;
    } else if(blk==2){
        float v=0.f;
        if(lane<9) v=sp_(Wsd[t*6+(lane/3)*2+((lane%3)==1)]);
        float s=wsum_(v);
        if(lane<9) g_wsd[t*9+lane]=v/s;
        if(lane==0){
            float s0=sig_(Wprop[t*3+0]), s1=sig_(Wprop[t*3+1]), s2=sig_(Wprop[t*3+2]);
            g_wprop[t*4+0]=s1; g_wprop[t*4+1]=s0; g_wprop[t*4+2]=s1; g_wprop[t*4+3]=s2;
            float p0=sp_(Wpow[t*5+0]),p1=sp_(Wpow[t*5+1]),p2=sp_(Wpow[t*5+2]),
                  p3=sp_(Wpow[t*5+3]),p4=sp_(Wpow[t*5+4]);
            g_wpow0[t*4+0]=p0; g_wpow0[t*4+1]=p2; g_wpow0[t*4+2]=p1; g_wpow0[t*4+3]=p4;
            g_wpow1[t*4+0]=p1; g_wpow1[t*4+1]=p3; g_wpow1[t*4+2]=p0; g_wpow1[t*4+3]=p4;
        }
    } else if(blk==3){
        const int map[16]={0,1,2,3, 4,5,4,6, 2,1,0,3, 7,8,7,9};
        float v=0.f;
        if(lane<16) v=sp_(Wdir[t*10+map[lane]]);
        float s=v;
        s+=__shfl_xor_sync(0xffffffffu,s,1);
        s+=__shfl_xor_sync(0xffffffffu,s,2);
        if(lane<16) g_wdir[((lane>>2)*32+t)*4+(lane&3)]=v/s;
    } else {
        float v0=0.f,v1=0.f,v2=0.f,v3=0.f;
        if(lane<9){
            int h=lane/3,c=lane%3;
            v0=sp_(Wse0[t*9+lane]);
            v1=sp_(Wse1[t*6+h*2+(c==1)]);
            v2=sp_(Wse0[t*9+h*3+(2-c)]);
            v3=sp_(Wse3[t*6+h*2+(c==1)]);
        }
        float s0=wsum_(v0), s1=wsum_(v1), s2=wsum_(v2), s3=wsum_(v3);
        if(lane<9){
            g_wse[(t*4+0)*9+lane]=v0/s0;
            g_wse[(t*4+1)*9+lane]=v1/s1;
            g_wse[(t*4+2)*9+lane]=v2/s2;
            g_wse[(t*4+3)*9+lane]=v3/s3;
        }
    }
}

// ---------------- K1: vectorized, 8 px/thread ----------------
__global__ void __launch_bounds__(256) k1_prepin(const float* __restrict__ x,
                                                 const float* __restrict__ ece,
                                                 const float* __restrict__ ce)
{
    int plane = blockIdx.y;
    int i = plane & 31;
    int g = blockIdx.x*256 + threadIdx.x;
    int y = g/24, xg = (g - y*24)*8;
    const float* dcd = x + (size_t)plane*HW;
    const float* cdp = x + (size_t)(64+plane)*HW;

    float lv[3][10], cv[3][10];
#pragma unroll
    for(int r=0;r<3;r++){
        int yy=y-1+r;
        bool yok=((unsigned)yy<(unsigned)Hh);
        const float* rd0=dcd+yy*Ww;
        const float* rc0=cdp+yy*Ww;
        float rd[16],rc[16];
#pragma unroll
        for(int seg=0;seg<4;seg++){
            int xs=xg-4+seg*4;
            float4 vd=make_float4(0.f,0.f,0.f,0.f), vc=vd;
            if(yok&&(unsigned)xs<(unsigned)Ww){
                vd=*reinterpret_cast<const float4*>(rd0+xs);
                vc=*reinterpret_cast<const float4*>(rc0+xs);
            }
            rd[seg*4]=vd.x; rd[seg*4+1]=vd.y; rd[seg*4+2]=vd.z; rd[seg*4+3]=vd.w;
            rc[seg*4]=vc.x; rc[seg*4+1]=vc.y; rc[seg*4+2]=vc.z; rc[seg*4+3]=vc.w;
        }
#pragma unroll
        for(int idx=0;idx<10;idx++){
            float dc=rd[idx+3], c=rc[idx+3];
            cv[r][idx]=c;
            float l=__log2f(dc)-__log2f(c+EPSV);
            lv[r][idx]=(dc>0.f)? l : -1e30f;
        }
    }
    const int Ar[4]={0,0,0,1}, Ac[4]={0,1,2,2};
    const int Br[4]={2,2,2,1}, Bc[4]={2,1,0,0};
    size_t base=(size_t)plane*4*HW + y*Ww + xg;
#pragma unroll
    for(int d=0;d<4;d++){
        float p0=g_wpow0[i*4+d], p1=g_wpow1[i*4+d], wp=g_wprop[i*4+d];
        size_t off=base+(size_t)d*HW;
        float4 cea=*reinterpret_cast<const float4*>(ce+off);
        float4 ceb=*reinterpret_cast<const float4*>(ce+off+4);
        float4 eca=*reinterpret_cast<const float4*>(ece+off);
        float4 ecb=*reinterpret_cast<const float4*>(ece+off+4);
        float cei[8]={cea.x,cea.y,cea.z,cea.w,ceb.x,ceb.y,ceb.z,ceb.w};
        float eci[8]={eca.x,eca.y,eca.z,eca.w,ecb.x,ecb.y,ecb.z,ecb.w};
        float oc[8],oe[8];
#pragma unroll
        for(int j=0;j<8;j++){
            float lA=lv[Ar[d]][j+Ac[d]], lB=lv[Br[d]][j+Bc[d]];
            float la=fminf(fmaxf(lA-fmaxf(lB,L2EPS),L2EPS),0.f);
            float lb=fminf(fmaxf(lB-fmaxf(lA,L2EPS),L2EPS),0.f);
            float en=ex2_(fminf(p0*la,p1*lb));
            float cn=cv[Ar[d]][j+Ac[d]]*cv[Br[d]][j+Bc[d]];
            oc[j]=cei[j]*wp+cn*(1.f-wp);
            oe[j]=eci[j]*wp+en*cn*(1.f-wp);
        }
        *reinterpret_cast<float4*>(g_cein+off)   =make_float4(oc[0],oc[1],oc[2],oc[3]);
        *reinterpret_cast<float4*>(g_cein+off+4) =make_float4(oc[4],oc[5],oc[6],oc[7]);
        *reinterpret_cast<float4*>(g_ecein+off)  =make_float4(oe[0],oe[1],oe[2],oe[3]);
        *reinterpret_cast<float4*>(g_ecein+off+4)=make_float4(oe[4],oe[5],oe[6],oe[7]);
    }
}

// ---------------- K2: shuffle-halo phase A + packed-weight 4-o phase B ----------------
__global__ void __launch_bounds__(256,3) k2_conve(float* __restrict__ dout)
{
    __shared__ float4 sh4[64][33];
    __shared__ float sh_wse[1152];
    __shared__ float sh_wdir[512];
    __shared__ float4 sh_wceP[256];   // [ii][o4] = (w[o4][ii],w[o4+8][ii],w[o4+16][ii],w[o4+24][ii])
    int tid=threadIdx.x;
    for(int k=tid;k<1152;k+=256) sh_wse[k]=g_wse[k];
    for(int k=tid;k<512;k+=256)  sh_wdir[k]=g_wdir[k];
    {
        int ii=tid>>3, o4=tid&7;
        sh_wceP[tid]=make_float4(g_wce[o4*32+ii],g_wce[(o4+8)*32+ii],
                                 g_wce[(o4+16)*32+ii],g_wce[(o4+24)*32+ii]);
    }
    int t=blockIdx.x;
    int b=t/576; int rem=t-b*576;
    int y0=rem/3; int x0=(rem-y0*3)*64;
    int i=tid>>3, px8=tid&7;
    int xb=x0+px8*8;
    int o4=tid&7, pxp=tid>>3;    // phase B: 4 o's, 2 px
    __syncthreads();

    const size_t ece_off=(size_t)128*HW;
    const size_t ceo_off=(size_t)384*HW;

    for(int sel=0;sel<2;sel++){
        const float* __restrict__ in = sel ? g_ecein : g_cein;
        float tacc[4][8];
#pragma unroll
        for(int p=0;p<4;p++)
#pragma unroll
            for(int j=0;j<8;j++) tacc[p][j]=0.f;
#pragma unroll
        for(int d=0;d<4;d++){
            const float* ch = in + (size_t)((b*32+i)*4+d)*HW;
            const float* w = sh_wse + (i*4+d)*9;
            float s[8];
#pragma unroll
            for(int j=0;j<8;j++) s[j]=0.f;
#pragma unroll
            for(int ry=0;ry<3;ry++){
                int yy=y0+ry-1;
                bool yok=((unsigned)yy<(unsigned)Hh);
                const float* rp=ch+yy*Ww;
                float4 a=make_float4(0.f,0.f,0.f,0.f), bb=a;
                if(yok){
                    a =*reinterpret_cast<const float4*>(rp+xb);
                    bb=*reinterpret_cast<const float4*>(rp+xb+4);
                }
                float lf=__shfl_up_sync(0xffffffffu,bb.w,1);
                float rt=__shfl_down_sync(0xffffffffu,a.x,1);
                if(px8==0) lf=(yok&&xb>0)       ? rp[xb-1] : 0.f;
                if(px8==7) rt=(yok&&(xb+8)<Ww)  ? rp[xb+8] : 0.f;
                float r[10]={lf,a.x,a.y,a.z,a.w,bb.x,bb.y,bb.z,bb.w,rt};
                float w0=w[ry*3],w1=w[ry*3+1],w2=w[ry*3+2];
#pragma unroll
                for(int j=0;j<8;j++)
                    s[j]+=w0*r[j]+w1*r[j+1]+w2*r[j+2];
            }
#pragma unroll
            for(int p=0;p<4;p++){
                float wd=sh_wdir[(p*32+i)*4+d];
#pragma unroll
                for(int j=0;j<8;j++) tacc[p][j]+=wd*s[j];
            }
        }
#pragma unroll
        for(int j=0;j<8;j++)
            sh4[px8*8+j][i]=make_float4(tacc[0][j],tacc[1][j],tacc[2][j],tacc[3][j]);
        __syncthreads();

        // phase B: 4 o's (o4+8k) x 2 px (pxp*2, +1), packed weights
        float2 acc[4][4];   // [og][p], .x=px0 .y=px1
#pragma unroll
        for(int og=0;og<4;og++)
#pragma unroll
            for(int p=0;p<4;p++) acc[og][p]=make_float2(0.f,0.f);
#pragma unroll 4
        for(int ii=0;ii<32;ii++){
            float4 wv=sh_wceP[ii*8+o4];
            float4 t0=sh4[pxp*2  ][ii];
            float4 t1=sh4[pxp*2+1][ii];
            acc[0][0].x+=wv.x*t0.x; acc[0][0].y+=wv.x*t1.x;
            acc[0][1].x+=wv.x*t0.y; acc[0][1].y+=wv.x*t1.y;
            acc[0][2].x+=wv.x*t0.z; acc[0][2].y+=wv.x*t1.z;
            acc[0][3].x+=wv.x*t0.w; acc[0][3].y+=wv.x*t1.w;
            acc[1][0].x+=wv.y*t0.x; acc[1][0].y+=wv.y*t1.x;
            acc[1][1].x+=wv.y*t0.y; acc[1][1].y+=wv.y*t1.y;
            acc[1][2].x+=wv.y*t0.z; acc[1][2].y+=wv.y*t1.z;
            acc[1][3].x+=wv.y*t0.w; acc[1][3].y+=wv.y*t1.w;
            acc[2][0].x+=wv.z*t0.x; acc[2][0].y+=wv.z*t1.x;
            acc[2][1].x+=wv.z*t0.y; acc[2][1].y+=wv.z*t1.y;
            acc[2][2].x+=wv.z*t0.z; acc[2][2].y+=wv.z*t1.z;
            acc[2][3].x+=wv.z*t0.w; acc[2][3].y+=wv.z*t1.w;
            acc[3][0].x+=wv.w*t0.x; acc[3][0].y+=wv.w*t1.x;
            acc[3][1].x+=wv.w*t0.y; acc[3][1].y+=wv.w*t1.y;
            acc[3][2].x+=wv.w*t0.z; acc[3][2].y+=wv.w*t1.z;
            acc[3][3].x+=wv.w*t0.w; acc[3][3].y+=wv.w*t1.w;
        }
        size_t ooff = sel ? ece_off : ceo_off;
#pragma unroll
        for(int og=0;og<4;og++){
            int o=o4+og*8;
            float* op=dout+ooff+(size_t)((b*32+o)*4)*HW+y0*Ww+x0+pxp*2;
#pragma unroll
            for(int p=0;p<4;p++)
                *reinterpret_cast<float2*>(op+(size_t)p*HW)=acc[og][p];
        }
        __syncthreads();
    }
}

// ---------------- K3: 512 threads, shuffle-halo + packed-weight 4-o phase D ----------------
__global__ void __launch_bounds__(512,2) k3_final(const float* __restrict__ x,
                                                  float* __restrict__ dout)
{
    __shared__ float2 sh2[64][33];
    __shared__ float4 sh_wcdP[256];
    __shared__ float sh_wsd[288];
    int tid=threadIdx.x;
    if(tid<256){
        int ii=tid>>3, o4=tid&7;
        sh_wcdP[tid]=make_float4(g_wcd[o4*32+ii],g_wcd[(o4+8)*32+ii],
                                 g_wcd[(o4+16)*32+ii],g_wcd[(o4+24)*32+ii]);
    }
    for(int k=tid;k<288;k+=512)  sh_wsd[k]=g_wsd[k];
    int t=blockIdx.x;
    int b=t/576; int rem=t-b*576;
    int y0=rem/3; int x0=(rem-y0*3)*64;
    int i=tid>>4, pxg=tid&15;
    int xb=x0+pxg*4;
    int o4=tid&7, px=tid>>3;    // phase D: 4 o's, 1 px
    __syncthreads();

    const size_t ece_off=(size_t)128*HW;
    const size_t ceo_off=(size_t)384*HW;
    float e[5][4];
#pragma unroll
    for(int j=0;j<4;j++) e[4][j]=1.f;
    size_t pbase=(size_t)(b*32+i)*4*HW + y0*Ww + xb;
#pragma unroll
    for(int d=0;d<4;d++){
        float4 ev=*reinterpret_cast<const float4*>(dout+ece_off+pbase+(size_t)d*HW);
        float4 c4=*reinterpret_cast<const float4*>(dout+ceo_off+pbase+(size_t)d*HW);
        e[d][0]=fminf(fmaxf(__fdividef(ev.x,c4.x+EPSV),EPSV),1.f);
        e[d][1]=fminf(fmaxf(__fdividef(ev.y,c4.y+EPSV),EPSV),1.f);
        e[d][2]=fminf(fmaxf(__fdividef(ev.z,c4.z+EPSV),EPSV),1.f);
        e[d][3]=fminf(fmaxf(__fdividef(ev.w,c4.w+EPSV),EPSV),1.f);
    }
    const float* dcd=x+(size_t)(b*32+i)*HW;
    const float* cdp=x+(size_t)(64+b*32+i)*HW;
    const float* w=sh_wsd+i*9;
    float md[4]={0.f,0.f,0.f,0.f}, mc[4]={0.f,0.f,0.f,0.f};
    const int emap[9]={0,1,2,3,4,3,2,1,0};
#pragma unroll
    for(int ry=0;ry<3;ry++){
        int yy=y0+ry-1;
        bool yok=((unsigned)yy<(unsigned)Hh);
        const float* rpd=dcd+yy*Ww;
        const float* rpc=cdp+yy*Ww;
        float4 ad=make_float4(0.f,0.f,0.f,0.f), ac=ad;
        if(yok){
            ad=*reinterpret_cast<const float4*>(rpd+xb);
            ac=*reinterpret_cast<const float4*>(rpc+xb);
        }
        float lfd=__shfl_up_sync(0xffffffffu,ad.w,1);
        float lfc=__shfl_up_sync(0xffffffffu,ac.w,1);
        float rtd=__shfl_down_sync(0xffffffffu,ad.x,1);
        float rtc=__shfl_down_sync(0xffffffffu,ac.x,1);
        if(pxg==0){
            lfd=(yok&&xb>0)? rpd[xb-1]:0.f;
            lfc=(yok&&xb>0)? rpc[xb-1]:0.f;
        }
        if(pxg==15){
            rtd=(yok&&(xb+4)<Ww)? rpd[xb+4]:0.f;
            rtc=(yok&&(xb+4)<Ww)? rpc[xb+4]:0.f;
        }
        float rd[6]={lfd,ad.x,ad.y,ad.z,ad.w,rtd};
        float rc[6]={lfc,ac.x,ac.y,ac.z,ac.w,rtc};
#pragma unroll
        for(int rx=0;rx<3;rx++){
            int k=ry*3+rx;
            float wk=w[k];
#pragma unroll
            for(int j=0;j<4;j++){
                float f=wk*e[emap[k]][j];
                md[j]+=f*rd[j+rx];
                mc[j]+=f*rc[j+rx];
            }
        }
    }
#pragma unroll
    for(int j=0;j<4;j++) sh2[pxg*4+j][i]=make_float2(md[j],mc[j]);
    __syncthreads();

    // phase D: 4 o's x 1 px with packed weights
    float accd[4]={0.f,0.f,0.f,0.f}, accc[4]={0.f,0.f,0.f,0.f};
#pragma unroll 4
    for(int ii=0;ii<32;ii++){
        float4 wv=sh_wcdP[ii*8+o4];
        float2 v=sh2[px][ii];
        accd[0]+=wv.x*v.x; accc[0]+=wv.x*v.y;
        accd[1]+=wv.y*v.x; accc[1]+=wv.y*v.y;
        accd[2]+=wv.z*v.x; accc[2]+=wv.z*v.y;
        accd[3]+=wv.w*v.x; accc[3]+=wv.w*v.y;
    }
#pragma unroll
    for(int og=0;og<4;og++){
        int o=o4+og*8;
        dout[(size_t)(b*32+o)*HW+y0*Ww+x0+px]   =accd[og];
        dout[(size_t)(64+b*32+o)*HW+y0*Ww+x0+px]=accc[og];
    }
}

extern "C" void kernel_launch(void* const* d_in, const int* in_sizes, int n_in,
                              void* d_out, int out_size)
{
    const float* x   =(const float*)d_in[0];
    const float* ece =(const float*)d_in[1];
    const float* ce  =(const float*)d_in[2];
    prep_kernel<<<5,1024>>>((const float*)d_in[3],(const float*)d_in[4],
                            (const float*)d_in[5],(const float*)d_in[6],
                            (const float*)d_in[7],(const float*)d_in[8],
                            (const float*)d_in[9],(const float*)d_in[10],
                            (const float*)d_in[11]);
    k1_prepin<<<dim3(18,64),256>>>(x,ece,ce);
    k2_conve<<<1152,256>>>((float*)d_out);
    k3_final<<<1152,512>>>(x,(float*)d_out);
}

// round 8
// speedup vs baseline: 1.4095x; 1.1217x over previous
#include <cuda_runtime.h>
#include <math.h>

#define EPSV  1e-20f
#define L2EPS -66.438561897f
#define Hh 192
#define Ww 192
#define HW (Hh*Ww)

__device__ float g_wcd[1024];     // channel_d [o][i]
__device__ float g_wsd[288];      // spatial_d [i][k]
__device__ float g_wce[1024];     // channel_e [o][i]
__device__ float g_wdir[512];     // [p][i][d]
__device__ float g_wse[1152];     // [i][d][k]
__device__ float g_wprop[128];    // [i][d]
__device__ float g_wpow0[128];    // [i][d]
__device__ float g_wpow1[128];    // [i][d]

__device__ __forceinline__ float sp_(float v){ return log1pf(expf(v)); }
__device__ __forceinline__ float sig_(float v){ return 1.f/(1.f+expf(-v)); }
__device__ __forceinline__ float ex2_(float v){
    float r; asm("ex2.approx.f32 %0, %1;" : "=f"(r) : "f"(v)); return r;
}
__device__ __forceinline__ float wsum_(float v){
#pragma unroll
    for(int m=16;m;m>>=1) v+=__shfl_xor_sync(0xffffffffu,v,m);
    return v;
}

// ---------------- prep: 5 blocks x 32 warps ----------------
__global__ void prep_kernel(const float* __restrict__ Wcd, const float* __restrict__ Wsd,
                            const float* __restrict__ Wce, const float* __restrict__ Wse0,
                            const float* __restrict__ Wse1, const float* __restrict__ Wse3,
                            const float* __restrict__ Wdir, const float* __restrict__ Wpow,
                            const float* __restrict__ Wprop)
{
    int blk=blockIdx.x;
    int t=threadIdx.x>>5, lane=threadIdx.x&31;
    if(blk==0){
        float v=sp_(Wcd[t*32+lane]);
        float s=wsum_(v);
        g_wcd[t*32+lane]=v/s;
    } else if(blk==1){
        float v=sp_(Wce[t*32+lane]);
        float s=wsum_(v);
        g_wce[t*32+lane]=v/s;
    } else if(blk==2){
        float v=0.f;
        if(lane<9) v=sp_(Wsd[t*6+(lane/3)*2+((lane%3)==1)]);
        float s=wsum_(v);
        if(lane<9) g_wsd[t*9+lane]=v/s;
        if(lane==0){
            float s0=sig_(Wprop[t*3+0]), s1=sig_(Wprop[t*3+1]), s2=sig_(Wprop[t*3+2]);
            g_wprop[t*4+0]=s1; g_wprop[t*4+1]=s0; g_wprop[t*4+2]=s1; g_wprop[t*4+3]=s2;
            float p0=sp_(Wpow[t*5+0]),p1=sp_(Wpow[t*5+1]),p2=sp_(Wpow[t*5+2]),
                  p3=sp_(Wpow[t*5+3]),p4=sp_(Wpow[t*5+4]);
            g_wpow0[t*4+0]=p0; g_wpow0[t*4+1]=p2; g_wpow0[t*4+2]=p1; g_wpow0[t*4+3]=p4;
            g_wpow1[t*4+0]=p1; g_wpow1[t*4+1]=p3; g_wpow1[t*4+2]=p0; g_wpow1[t*4+3]=p4;
        }
    } else if(blk==3){
        const int map[16]={0,1,2,3, 4,5,4,6, 2,1,0,3, 7,8,7,9};
        float v=0.f;
        if(lane<16) v=sp_(Wdir[t*10+map[lane]]);
        float s=v;
        s+=__shfl_xor_sync(0xffffffffu,s,1);
        s+=__shfl_xor_sync(0xffffffffu,s,2);
        if(lane<16) g_wdir[((lane>>2)*32+t)*4+(lane&3)]=v/s;
    } else {
        float v0=0.f,v1=0.f,v2=0.f,v3=0.f;
        if(lane<9){
            int h=lane/3,c=lane%3;
            v0=sp_(Wse0[t*9+lane]);
            v1=sp_(Wse1[t*6+h*2+(c==1)]);
            v2=sp_(Wse0[t*9+h*3+(2-c)]);
            v3=sp_(Wse3[t*6+h*2+(c==1)]);
        }
        float s0=wsum_(v0), s1=wsum_(v1), s2=wsum_(v2), s3=wsum_(v3);
        if(lane<9){
            g_wse[(t*4+0)*9+lane]=v0/s0;
            g_wse[(t*4+1)*9+lane]=v1/s1;
            g_wse[(t*4+2)*9+lane]=v2/s2;
            g_wse[(t*4+3)*9+lane]=v3/s3;
        }
    }
}

// Load one x-row window (8 cols xb-2..xb+5) of (log-ratio, cd) into LV/CV.
#define LOAD_ROW(yy, LV, CV) do{                                              \
    int yy_=(yy);                                                             \
    bool yok_=((unsigned)yy_<(unsigned)Hh);                                   \
    const float* rpd_=dcd+yy_*Ww;                                             \
    const float* rpc_=cdp+yy_*Ww;                                             \
    float4 xd_=make_float4(0.f,0.f,0.f,0.f), xc_=xd_;                         \
    if(yok_){ xd_=*reinterpret_cast<const float4*>(rpd_+xb);                  \
              xc_=*reinterpret_cast<const float4*>(rpc_+xb); }                \
    float dm2_=__shfl_up_sync(0xffffffffu,xd_.z,1);                           \
    float dm1_=__shfl_up_sync(0xffffffffu,xd_.w,1);                           \
    float cm2_=__shfl_up_sync(0xffffffffu,xc_.z,1);                           \
    float cm1_=__shfl_up_sync(0xffffffffu,xc_.w,1);                           \
    float dp4_=__shfl_down_sync(0xffffffffu,xd_.x,1);                         \
    float dp5_=__shfl_down_sync(0xffffffffu,xd_.y,1);                         \
    float cp4_=__shfl_down_sync(0xffffffffu,xc_.x,1);                         \
    float cp5_=__shfl_down_sync(0xffffffffu,xc_.y,1);                         \
    if(pq==0){                                                                \
        dm2_=(yok_&&xb>=2)? rpd_[xb-2]:0.f;                                   \
        dm1_=(yok_&&xb>=1)? rpd_[xb-1]:0.f;                                   \
        cm2_=(yok_&&xb>=2)? rpc_[xb-2]:0.f;                                   \
        cm1_=(yok_&&xb>=1)? rpc_[xb-1]:0.f;                                   \
    }                                                                         \
    if(pq==7){                                                                \
        dp4_=(yok_&&(xb+4)<Ww)? rpd_[xb+4]:0.f;                               \
        dp5_=(yok_&&(xb+5)<Ww)? rpd_[xb+5]:0.f;                               \
        cp4_=(yok_&&(xb+4)<Ww)? rpc_[xb+4]:0.f;                               \
        cp5_=(yok_&&(xb+5)<Ww)? rpc_[xb+5]:0.f;                               \
    }                                                                         \
    float dv_[8]={dm2_,dm1_,xd_.x,xd_.y,xd_.z,xd_.w,dp4_,dp5_};               \
    float cw_[8]={cm2_,cm1_,xc_.x,xc_.y,xc_.z,xc_.w,cp4_,cp5_};               \
    _Pragma("unroll")                                                         \
    for(int m_=0;m_<8;m_++){                                                  \
        CV[m_]=cw_[m_];                                                       \
        float l_=__log2f(dv_[m_])-__log2f(cw_[m_]+EPSV);                      \
        LV[m_]=(dv_[m_]>0.f)? l_ : -1e30f;                                    \
    }                                                                         \
}while(0)

// ---------------- K2 fused: k1-on-the-fly + depthwise + dir mix + channel mix ----------------
__global__ void __launch_bounds__(256,2) k2f(const float* __restrict__ x,
                                             const float* __restrict__ ece,
                                             const float* __restrict__ ce,
                                             float* __restrict__ dout)
{
    __shared__ float sh_c[4*1056];     // [p][px*33+i]
    __shared__ float sh_e[4*1056];
    __shared__ float sh_wse[1152];
    __shared__ float sh_wdir[512];
    __shared__ float4 sh_wceP[256];    // [ii*8+o4]
    __shared__ float sh_wprop[128], sh_wp0[128], sh_wp1[128];
    int tid=threadIdx.x;
    for(int k=tid;k<1152;k+=256) sh_wse[k]=g_wse[k];
    for(int k=tid;k<512;k+=256)  sh_wdir[k]=g_wdir[k];
    {
        int ii=tid>>3, o4=tid&7;
        sh_wceP[tid]=make_float4(g_wce[o4*32+ii],g_wce[(o4+8)*32+ii],
                                 g_wce[(o4+16)*32+ii],g_wce[(o4+24)*32+ii]);
    }
    if(tid<128){ sh_wprop[tid]=g_wprop[tid]; sh_wp0[tid]=g_wpow0[tid]; sh_wp1[tid]=g_wpow1[tid]; }

    int t=blockIdx.x;
    int b=t/1152; int rem=t-b*1152;
    int y0=rem/6; int x0=(rem-y0*6)*32;
    int i=tid>>3, pq=tid&7;
    int xb=x0+pq*4;
    __syncthreads();

    const float* dcd=x+(size_t)(b*32+i)*HW;
    const float* cdp=x+(size_t)(64+b*32+i)*HW;

    // rolling window slots: lv0/cv0, lv1/cv1, lv2/cv2
    float lv0[8],lv1[8],lv2[8],cv0[8],cv1[8],cv2[8];
    LOAD_ROW(y0-2,lv0,cv0);
    LOAD_ROW(y0-1,lv1,cv1);
    LOAD_ROW(y0  ,lv2,cv2);

    float s_c[4][4], s_e[4][4];
#pragma unroll
    for(int d=0;d<4;d++)
#pragma unroll
        for(int j=0;j<4;j++){ s_c[d][j]=0.f; s_e[d][j]=0.f; }

    const int dA[4]={0,1,2,2};
    const int dB[4]={2,1,0,0};

#pragma unroll
    for(int ry=0;ry<3;ry++){
        int yy=y0-1+ry;
        bool row_ok=((unsigned)yy<(unsigned)Hh);
        // slot ptr selection (compile-time with unrolled ry)
        const float* LVm1 = (ry==0)? lv0 : (ry==1)? lv1 : lv2;
        const float* CVm1 = (ry==0)? cv0 : (ry==1)? cv1 : cv2;
        const float* LV0  = (ry==0)? lv1 : (ry==1)? lv2 : lv0;
        const float* CV0  = (ry==0)? cv1 : (ry==1)? cv2 : cv0;
        const float* LVp1 = (ry==0)? lv2 : (ry==1)? lv0 : lv1;
        const float* CVp1 = (ry==0)? cv2 : (ry==1)? cv0 : cv1;
        if(row_ok){
#pragma unroll
            for(int d=0;d<4;d++){
                size_t poff=(size_t)((b*32+i)*4+d)*HW + (size_t)yy*Ww;
                float4 ce4=*reinterpret_cast<const float4*>(ce+poff+xb);
                float4 ec4=*reinterpret_cast<const float4*>(ece+poff+xb);
                float cem1=__shfl_up_sync(0xffffffffu,ce4.w,1);
                float ecm1=__shfl_up_sync(0xffffffffu,ec4.w,1);
                float cep4=__shfl_down_sync(0xffffffffu,ce4.x,1);
                float ecp4=__shfl_down_sync(0xffffffffu,ec4.x,1);
                if(pq==0){
                    cem1=(xb>=1)? ce[poff+xb-1]:0.f;
                    ecm1=(xb>=1)? ece[poff+xb-1]:0.f;
                }
                if(pq==7){
                    cep4=((xb+4)<Ww)? ce[poff+xb+4]:0.f;
                    ecp4=((xb+4)<Ww)? ece[poff+xb+4]:0.f;
                }
                float cevv[6]={cem1,ce4.x,ce4.y,ce4.z,ce4.w,cep4};
                float ecvv[6]={ecm1,ec4.x,ec4.y,ec4.z,ec4.w,ecp4};
                float wp=sh_wprop[i*4+d], p0=sh_wp0[i*4+d], p1=sh_wp1[i*4+d];
                const float* LA=(d<3)? LVm1 : LV0;
                const float* CA=(d<3)? CVm1 : CV0;
                const float* LB=(d<3)? LVp1 : LV0;
                const float* CB=(d<3)? CVp1 : CV0;
                float cein[6],ecein[6];
#pragma unroll
                for(int k=0;k<6;k++){
                    int q=xb-1+k;
                    bool vq=((unsigned)q<(unsigned)Ww);
                    float lA=LA[k+dA[d]], lB=LB[k+dB[d]];
                    float la=fminf(fmaxf(lA-fmaxf(lB,L2EPS),L2EPS),0.f);
                    float lb=fminf(fmaxf(lB-fmaxf(lA,L2EPS),L2EPS),0.f);
                    float en=ex2_(fminf(p0*la,p1*lb));
                    float cn=CA[k+dA[d]]*CB[k+dB[d]];
                    cein[k] =vq? (cevv[k]*wp+cn*(1.f-wp))    : 0.f;
                    ecein[k]=vq? (ecvv[k]*wp+en*cn*(1.f-wp)) : 0.f;
                }
                const float* w=sh_wse+(i*4+d)*9;
                float w0=w[ry*3],w1=w[ry*3+1],w2=w[ry*3+2];
#pragma unroll
                for(int j=0;j<4;j++){
                    s_c[d][j]+=w0*cein[j]+w1*cein[j+1]+w2*cein[j+2];
                    s_e[d][j]+=w0*ecein[j]+w1*ecein[j+1]+w2*ecein[j+2];
                }
            }
        }
        if(ry==0) LOAD_ROW(y0+1,lv0,cv0);
        if(ry==1) LOAD_ROW(y0+2,lv1,cv1);
    }

    // dir mix -> staging (scalar, conflict-free)
#pragma unroll
    for(int p=0;p<4;p++){
        float wd0=sh_wdir[(p*32+i)*4+0];
        float wd1=sh_wdir[(p*32+i)*4+1];
        float wd2=sh_wdir[(p*32+i)*4+2];
        float wd3=sh_wdir[(p*32+i)*4+3];
#pragma unroll
        for(int j=0;j<4;j++){
            float tc=wd0*s_c[0][j]+wd1*s_c[1][j]+wd2*s_c[2][j]+wd3*s_c[3][j];
            float te=wd0*s_e[0][j]+wd1*s_e[1][j]+wd2*s_e[2][j]+wd3*s_e[3][j];
            sh_c[p*1056+(pq*4+j)*33+i]=tc;
            sh_e[p*1056+(pq*4+j)*33+i]=te;
        }
    }
    __syncthreads();

    // channel mix: warp = one o4, 32 px; 4 o's via packed weights
    int o4=tid>>5, px=tid&31;
    float accc[4][4], acce[4][4];
#pragma unroll
    for(int og=0;og<4;og++)
#pragma unroll
        for(int p=0;p<4;p++){ accc[og][p]=0.f; acce[og][p]=0.f; }
#pragma unroll 4
    for(int ii=0;ii<32;ii++){
        float4 wv=sh_wceP[ii*8+o4];
#pragma unroll
        for(int p=0;p<4;p++){
            float tc=sh_c[p*1056+px*33+ii];
            float te=sh_e[p*1056+px*33+ii];
            accc[0][p]+=wv.x*tc; acce[0][p]+=wv.x*te;
            accc[1][p]+=wv.y*tc; acce[1][p]+=wv.y*te;
            accc[2][p]+=wv.z*tc; acce[2][p]+=wv.z*te;
            accc[3][p]+=wv.w*tc; acce[3][p]+=wv.w*te;
        }
    }
    const size_t ece_off=(size_t)128*HW;
    const size_t ceo_off=(size_t)384*HW;
#pragma unroll
    for(int og=0;og<4;og++){
        int o=o4+og*8;
        size_t base=(size_t)((b*32+o)*4)*HW + (size_t)y0*Ww + x0 + px;
#pragma unroll
        for(int p=0;p<4;p++){
            dout[ece_off+base+(size_t)p*HW]=acce[og][p];
            dout[ceo_off+base+(size_t)p*HW]=accc[og][p];
        }
    }
}

// ---------------- K3: 512 threads, shuffle-halo + packed-weight 4-o phase D ----------------
__global__ void __launch_bounds__(512,2) k3_final(const float* __restrict__ x,
                                                  float* __restrict__ dout)
{
    __shared__ float2 sh2[64][33];
    __shared__ float4 sh_wcdP[256];
    __shared__ float sh_wsd[288];
    int tid=threadIdx.x;
    if(tid<256){
        int ii=tid>>3, o4=tid&7;
        sh_wcdP[tid]=make_float4(g_wcd[o4*32+ii],g_wcd[(o4+8)*32+ii],
                                 g_wcd[(o4+16)*32+ii],g_wcd[(o4+24)*32+ii]);
    }
    for(int k=tid;k<288;k+=512)  sh_wsd[k]=g_wsd[k];
    int t=blockIdx.x;
    int b=t/576; int rem=t-b*576;
    int y0=rem/3; int x0=(rem-y0*3)*64;
    int i=tid>>4, pxg=tid&15;
    int xb=x0+pxg*4;
    int o4=tid&7, px=tid>>3;
    __syncthreads();

    const size_t ece_off=(size_t)128*HW;
    const size_t ceo_off=(size_t)384*HW;
    float e[5][4];
#pragma unroll
    for(int j=0;j<4;j++) e[4][j]=1.f;
    size_t pbase=(size_t)(b*32+i)*4*HW + y0*Ww + xb;
#pragma unroll
    for(int d=0;d<4;d++){
        float4 ev=*reinterpret_cast<const float4*>(dout+ece_off+pbase+(size_t)d*HW);
        float4 c4=*reinterpret_cast<const float4*>(dout+ceo_off+pbase+(size_t)d*HW);
        e[d][0]=fminf(fmaxf(__fdividef(ev.x,c4.x+EPSV),EPSV),1.f);
        e[d][1]=fminf(fmaxf(__fdividef(ev.y,c4.y+EPSV),EPSV),1.f);
        e[d][2]=fminf(fmaxf(__fdividef(ev.z,c4.z+EPSV),EPSV),1.f);
        e[d][3]=fminf(fmaxf(__fdividef(ev.w,c4.w+EPSV),EPSV),1.f);
    }
    const float* dcd=x+(size_t)(b*32+i)*HW;
    const float* cdp=x+(size_t)(64+b*32+i)*HW;
    const float* w=sh_wsd+i*9;
    float md[4]={0.f,0.f,0.f,0.f}, mc[4]={0.f,0.f,0.f,0.f};
    const int emap[9]={0,1,2,3,4,3,2,1,0};
#pragma unroll
    for(int ry=0;ry<3;ry++){
        int yy=y0+ry-1;
        bool yok=((unsigned)yy<(unsigned)Hh);
        const float* rpd=dcd+yy*Ww;
        const float* rpc=cdp+yy*Ww;
        float4 ad=make_float4(0.f,0.f,0.f,0.f), ac=ad;
        if(yok){
            ad=*reinterpret_cast<const float4*>(rpd+xb);
            ac=*reinterpret_cast<const float4*>(rpc+xb);
        }
        float lfd=__shfl_up_sync(0xffffffffu,ad.w,1);
        float lfc=__shfl_up_sync(0xffffffffu,ac.w,1);
        float rtd=__shfl_down_sync(0xffffffffu,ad.x,1);
        float rtc=__shfl_down_sync(0xffffffffu,ac.x,1);
        if(pxg==0){
            lfd=(yok&&xb>0)? rpd[xb-1]:0.f;
            lfc=(yok&&xb>0)? rpc[xb-1]:0.f;
        }
        if(pxg==15){
            rtd=(yok&&(xb+4)<Ww)? rpd[xb+4]:0.f;
            rtc=(yok&&(xb+4)<Ww)? rpc[xb+4]:0.f;
        }
        float rd[6]={lfd,ad.x,ad.y,ad.z,ad.w,rtd};
        float rc[6]={lfc,ac.x,ac.y,ac.z,ac.w,rtc};
#pragma unroll
        for(int rx=0;rx<3;rx++){
            int k=ry*3+rx;
            float wk=w[k];
#pragma unroll
            for(int j=0;j<4;j++){
                float f=wk*e[emap[k]][j];
                md[j]+=f*rd[j+rx];
                mc[j]+=f*rc[j+rx];
            }
        }
    }
#pragma unroll
    for(int j=0;j<4;j++) sh2[pxg*4+j][i]=make_float2(md[j],mc[j]);
    __syncthreads();

    float accd[4]={0.f,0.f,0.f,0.f}, accc2[4]={0.f,0.f,0.f,0.f};
#pragma unroll 4
    for(int ii=0;ii<32;ii++){
        float4 wv=sh_wcdP[ii*8+o4];
        float2 v=sh2[px][ii];
        accd[0]+=wv.x*v.x; accc2[0]+=wv.x*v.y;
        accd[1]+=wv.y*v.x; accc2[1]+=wv.y*v.y;
        accd[2]+=wv.z*v.x; accc2[2]+=wv.z*v.y;
        accd[3]+=wv.w*v.x; accc2[3]+=wv.w*v.y;
    }
#pragma unroll
    for(int og=0;og<4;og++){
        int o=o4+og*8;
        dout[(size_t)(b*32+o)*HW+y0*Ww+x0+px]   =accd[og];
        dout[(size_t)(64+b*32+o)*HW+y0*Ww+x0+px]=accc2[og];
    }
}

extern "C" void kernel_launch(void* const* d_in, const int* in_sizes, int n_in,
                              void* d_out, int out_size)
{
    const float* x   =(const float*)d_in[0];
    const float* ece =(const float*)d_in[1];
    const float* ce  =(const float*)d_in[2];
    prep_kernel<<<5,1024>>>((const float*)d_in[3],(const float*)d_in[4],
                            (const float*)d_in[5],(const float*)d_in[6],
                            (const float*)d_in[7],(const float*)d_in[8],
                            (const float*)d_in[9],(const float*)d_in[10],
                            (const float*)d_in[11]);
    k2f<<<2304,256>>>(x,ece,ce,(float*)d_out);
    k3_final<<<1152,512>>>(x,(float*)d_out);
}